// round 6
// baseline (speedup 1.0000x reference)
#include <cuda_runtime.h>
#include <math.h>

#define BN   20800
#define T_   24
#define F_   64
#define H_   128
#define H2_  256
#define H3_  384
#define TR   48            // rows per CTA
#define TRP2 98            // padded duplicated smem row stride (2*TR + 2, even)
#define RPT  6             // rows per thread
#define NCTA ((BN + TR - 1) / TR)   // 434

typedef unsigned long long ull;

// packed f32x2 FMA: d = a*b + c elementwise on two packed fp32
#define FMA2(d, a, b, c) \
    asm("fma.rn.f32x2 %0, %1, %2, %3;" : "=l"(d) : "l"(a), "l"(b), "l"(c))
#define UNPK2(lo, hi, v) \
    asm("mov.b64 {%0, %1}, %2;" : "=f"(lo), "=f"(hi) : "l"(v))
#define PACK2(d, lo, hi) \
    asm("mov.b64 %0, {%1, %2};" : "=l"(d) : "f"(lo), "f"(hi))

// scratch: layer-0 output sequence [BN][T][H]
__device__ float g_seq1[(size_t)BN * T_ * H_];
// pre-transposed weights: [k][c]
__device__ float g_wihT[F_ * H3_];
__device__ float g_whhT[H_ * H3_];
__device__ float g_gwT[H2_ * H2_];
__device__ float g_owT[H2_ * H_];

__global__ void transpose_weights(const float* __restrict__ w_ih,
                                  const float* __restrict__ w_hh,
                                  const float* __restrict__ gate_w,
                                  const float* __restrict__ out_w)
{
    int idx = blockIdx.x * blockDim.x + threadIdx.x;
    if (idx < H3_ * F_)  { int c = idx / F_,  k = idx % F_;  g_wihT[k * H3_ + c] = w_ih[idx]; }
    if (idx < H3_ * H_)  { int c = idx / H_,  k = idx % H_;  g_whhT[k * H3_ + c] = w_hh[idx]; }
    if (idx < H2_ * H2_) { int c = idx / H2_, k = idx % H2_; g_gwT[k * H2_ + c] = gate_w[idx]; }
    if (idx < H_ * H2_)  { int c = idx / H2_, k = idx % H2_; g_owT[k * H_ + c] = out_w[idx]; }
}

__device__ __forceinline__ float sigmoidf_(float v) {
    return __fdividef(1.0f, 1.0f + __expf(-v));
}
__device__ __forceinline__ float tanhf_(float v) {
    return __fdividef(2.0f, 1.0f + __expf(-2.0f * v)) - 1.0f;
}

#define ZERO6x2(A)                                    \
    _Pragma("unroll")                                 \
    for (int i = 0; i < RPT; ++i) {                   \
        (A)[i][0] = 0ULL; (A)[i][1] = 0ULL;           \
    }

#define UNPACK6x2(F, A)                               \
    _Pragma("unroll")                                 \
    for (int i = 0; i < RPT; ++i) {                   \
        UNPK2((F)[i][0], (F)[i][1], (A)[i][0]);       \
        UNPK2((F)[i][2], (F)[i][3], (A)[i][1]);       \
    }

// ---------------- Layer 0: torch GRUCell over T steps ----------------
// Fused-gate GEMM: one pass over x (K=64) and one over h (K=128); each k
// loads the activation ONCE (6 broadcast LDS.64) and three weight float4s
// (r/z/n column blocks). r,z accumulate x+h jointly; n kept split.
__global__ __launch_bounds__(256, 1)
void gru_layer0(const float* __restrict__ x,
                const float* __restrict__ b_ih,
                const float* __restrict__ b_hh)
{
    __shared__ __align__(16) float x_s[F_ * TRP2];   // x_t transposed+duplicated [f][2r]
    __shared__ __align__(16) float h_s[H_ * TRP2];   // h transposed+duplicated [k][2r]

    const int tid   = threadIdx.x;
    const int rg    = tid >> 5, cg = tid & 31;
    const int row0  = rg * RPT;
    const int row0d = row0 * 2;
    const int c4    = cg * 4;
    const int bn0   = blockIdx.x * TR;

    for (int i = tid; i < H_ * TRP2; i += 256) h_s[i] = 0.0f;

    float br[4], bz[4], bi_n[4], bh_n[4];
    #pragma unroll
    for (int j = 0; j < 4; ++j) {
        br[j]   = b_ih[c4 + j]        + b_hh[c4 + j];
        bz[j]   = b_ih[H_ + c4 + j]   + b_hh[H_ + c4 + j];
        bi_n[j] = b_ih[2 * H_ + c4 + j];
        bh_n[j] = b_hh[2 * H_ + c4 + j];
    }

    for (int t = 0; t < T_; ++t) {
        // load x_t tile (48 rows x 64 f), transposed + duplicated into smem
        #pragma unroll
        for (int u = 0; u < 3; ++u) {
            int idx = tid + u * 256;       // 0..767 float4 slots
            int r = idx >> 4;
            int f = (idx & 15) * 4;
            float4 v = make_float4(0.f, 0.f, 0.f, 0.f);
            int bn = bn0 + r;
            if (bn < BN)
                v = *reinterpret_cast<const float4*>(x + ((size_t)bn * T_ + t) * F_ + f);
            ull p;
            PACK2(p, v.x, v.x); *reinterpret_cast<ull*>(&x_s[(f + 0) * TRP2 + 2 * r]) = p;
            PACK2(p, v.y, v.y); *reinterpret_cast<ull*>(&x_s[(f + 1) * TRP2 + 2 * r]) = p;
            PACK2(p, v.z, v.z); *reinterpret_cast<ull*>(&x_s[(f + 2) * TRP2 + 2 * r]) = p;
            PACK2(p, v.w, v.w); *reinterpret_cast<ull*>(&x_s[(f + 3) * TRP2 + 2 * r]) = p;
        }
        __syncthreads();   // x_s ready; h_s writes from prev step visible

        ull aR[RPT][2], aZ[RPT][2], aNx[RPT][2], aNh[RPT][2];
        ZERO6x2(aR); ZERO6x2(aZ); ZERO6x2(aNx); ZERO6x2(aNh);

        // ---- x-part: gi (all 3 gates), K = 64 ----
        #pragma unroll 4
        for (int k = 0; k < F_; ++k) {
            const float* wrow = g_wihT + (size_t)k * H3_ + c4;
            ulonglong2 w0 = __ldg(reinterpret_cast<const ulonglong2*>(wrow));
            ulonglong2 w1 = __ldg(reinterpret_cast<const ulonglong2*>(wrow + H_));
            ulonglong2 w2 = __ldg(reinterpret_cast<const ulonglong2*>(wrow + 2 * H_));
            const float* ap = x_s + k * TRP2 + row0d;
            ull a2[RPT];
            #pragma unroll
            for (int i = 0; i < RPT; ++i)
                a2[i] = *reinterpret_cast<const ull*>(ap + 2 * i);
            #pragma unroll
            for (int i = 0; i < RPT; ++i) {
                FMA2(aR[i][0],  a2[i], w0.x, aR[i][0]);
                FMA2(aR[i][1],  a2[i], w0.y, aR[i][1]);
                FMA2(aZ[i][0],  a2[i], w1.x, aZ[i][0]);
                FMA2(aZ[i][1],  a2[i], w1.y, aZ[i][1]);
                FMA2(aNx[i][0], a2[i], w2.x, aNx[i][0]);
                FMA2(aNx[i][1], a2[i], w2.y, aNx[i][1]);
            }
        }

        // ---- h-part: gh (r,z joined into aR/aZ; n separate), K = 128 ----
        #pragma unroll 4
        for (int k = 0; k < H_; ++k) {
            const float* wrow = g_whhT + (size_t)k * H3_ + c4;
            ulonglong2 w0 = __ldg(reinterpret_cast<const ulonglong2*>(wrow));
            ulonglong2 w1 = __ldg(reinterpret_cast<const ulonglong2*>(wrow + H_));
            ulonglong2 w2 = __ldg(reinterpret_cast<const ulonglong2*>(wrow + 2 * H_));
            const float* ap = h_s + k * TRP2 + row0d;
            ull a2[RPT];
            #pragma unroll
            for (int i = 0; i < RPT; ++i)
                a2[i] = *reinterpret_cast<const ull*>(ap + 2 * i);
            #pragma unroll
            for (int i = 0; i < RPT; ++i) {
                FMA2(aR[i][0],  a2[i], w0.x, aR[i][0]);
                FMA2(aR[i][1],  a2[i], w0.y, aR[i][1]);
                FMA2(aZ[i][0],  a2[i], w1.x, aZ[i][0]);
                FMA2(aZ[i][1],  a2[i], w1.y, aZ[i][1]);
                FMA2(aNh[i][0], a2[i], w2.x, aNh[i][0]);
                FMA2(aNh[i][1], a2[i], w2.y, aNh[i][1]);
            }
        }

        float fR[RPT][4], fZ[RPT][4], fNx[RPT][4], fNh[RPT][4];
        UNPACK6x2(fR, aR); UNPACK6x2(fZ, aZ);
        UNPACK6x2(fNx, aNx); UNPACK6x2(fNh, aNh);

        float hn[RPT][4];
        #pragma unroll
        for (int i = 0; i < RPT; ++i)
            #pragma unroll
            for (int j = 0; j < 4; ++j) {
                float hold = h_s[(c4 + j) * TRP2 + 2 * (row0 + i)];
                float rr = sigmoidf_(fR[i][j] + br[j]);
                float zz = sigmoidf_(fZ[i][j] + bz[j]);
                float n  = tanhf_(fNx[i][j] + bi_n[j] + rr * (fNh[i][j] + bh_n[j]));
                hn[i][j] = (1.f - zz) * n + zz * hold;
            }
        __syncthreads();   // all reads of h_s / x_s done

        #pragma unroll
        for (int i = 0; i < RPT; ++i) {
            #pragma unroll
            for (int j = 0; j < 4; ++j) {
                ull p;
                PACK2(p, hn[i][j], hn[i][j]);
                *reinterpret_cast<ull*>(&h_s[(c4 + j) * TRP2 + 2 * (row0 + i)]) = p;
            }
            int bn = bn0 + row0 + i;
            if (bn < BN)
                *reinterpret_cast<float4*>(g_seq1 + ((size_t)bn * T_ + t) * H_ + c4)
                    = make_float4(hn[i][0], hn[i][1], hn[i][2], hn[i][3]);
        }
        // next iteration's post-load __syncthreads orders these writes vs. reads
    }
}

// ---------------- Layer 1: custom GRUCell over T steps ----------------
// Fused r,z gate GEMM (lane owns cols c4 and c4+128 of the 256 gate outputs);
// candidate GEMM separate (depends on r).
__global__ __launch_bounds__(256, 1)
void gru_layer1(const float* __restrict__ gate_b,
                const float* __restrict__ out_b,
                float* __restrict__ out)
{
    __shared__ __align__(16) float x_s[H_ * TRP2];
    __shared__ __align__(16) float h_s[H_ * TRP2];
    __shared__ __align__(16) float rh_s[H_ * TRP2];

    const int tid   = threadIdx.x;
    const int rg    = tid >> 5, cg = tid & 31;
    const int row0  = rg * RPT;
    const int row0d = row0 * 2;
    const int c4    = cg * 4;
    const int bn0   = blockIdx.x * TR;

    for (int i = tid; i < H_ * TRP2; i += 256) h_s[i] = 0.0f;

    float bgr[4], bgz[4], bo[4];
    #pragma unroll
    for (int j = 0; j < 4; ++j) {
        bgr[j] = gate_b[c4 + j];
        bgz[j] = gate_b[H_ + c4 + j];
        bo[j]  = out_b[c4 + j];
    }

    for (int t = 0; t < T_; ++t) {
        // load x_t = seq1[:, t, :] tile (48 x 128), transposed + duplicated
        #pragma unroll
        for (int u = 0; u < 6; ++u) {
            int idx = tid + u * 256;    // 0..1535 float4 slots
            int r = idx >> 5;
            int f = (idx & 31) * 4;
            float4 v = make_float4(0.f, 0.f, 0.f, 0.f);
            int bn = bn0 + r;
            if (bn < BN)
                v = *reinterpret_cast<const float4*>(g_seq1 + ((size_t)bn * T_ + t) * H_ + f);
            ull p;
            PACK2(p, v.x, v.x); *reinterpret_cast<ull*>(&x_s[(f + 0) * TRP2 + 2 * r]) = p;
            PACK2(p, v.y, v.y); *reinterpret_cast<ull*>(&x_s[(f + 1) * TRP2 + 2 * r]) = p;
            PACK2(p, v.z, v.z); *reinterpret_cast<ull*>(&x_s[(f + 2) * TRP2 + 2 * r]) = p;
            PACK2(p, v.w, v.w); *reinterpret_cast<ull*>(&x_s[(f + 3) * TRP2 + 2 * r]) = p;
        }
        __syncthreads();

        ull aR[RPT][2], aZ[RPT][2];
        ZERO6x2(aR); ZERO6x2(aZ);

        // ---- gates: x-part (gate_w rows 0..127) ----
        #pragma unroll 4
        for (int k = 0; k < H_; ++k) {
            const float* wrow = g_gwT + (size_t)k * H2_ + c4;
            ulonglong2 w0 = __ldg(reinterpret_cast<const ulonglong2*>(wrow));
            ulonglong2 w1 = __ldg(reinterpret_cast<const ulonglong2*>(wrow + H_));
            const float* ap = x_s + k * TRP2 + row0d;
            ull a2[RPT];
            #pragma unroll
            for (int i = 0; i < RPT; ++i)
                a2[i] = *reinterpret_cast<const ull*>(ap + 2 * i);
            #pragma unroll
            for (int i = 0; i < RPT; ++i) {
                FMA2(aR[i][0], a2[i], w0.x, aR[i][0]);
                FMA2(aR[i][1], a2[i], w0.y, aR[i][1]);
                FMA2(aZ[i][0], a2[i], w1.x, aZ[i][0]);
                FMA2(aZ[i][1], a2[i], w1.y, aZ[i][1]);
            }
        }
        // ---- gates: h-part (gate_w rows 128..255) ----
        #pragma unroll 4
        for (int k = 0; k < H_; ++k) {
            const float* wrow = g_gwT + (size_t)(H_ + k) * H2_ + c4;
            ulonglong2 w0 = __ldg(reinterpret_cast<const ulonglong2*>(wrow));
            ulonglong2 w1 = __ldg(reinterpret_cast<const ulonglong2*>(wrow + H_));
            const float* ap = h_s + k * TRP2 + row0d;
            ull a2[RPT];
            #pragma unroll
            for (int i = 0; i < RPT; ++i)
                a2[i] = *reinterpret_cast<const ull*>(ap + 2 * i);
            #pragma unroll
            for (int i = 0; i < RPT; ++i) {
                FMA2(aR[i][0], a2[i], w0.x, aR[i][0]);
                FMA2(aR[i][1], a2[i], w0.y, aR[i][1]);
                FMA2(aZ[i][0], a2[i], w1.x, aZ[i][0]);
                FMA2(aZ[i][1], a2[i], w1.y, aZ[i][1]);
            }
        }

        float fR[RPT][4], fZ[RPT][4];
        UNPACK6x2(fR, aR); UNPACK6x2(fZ, aZ);

        // r * h into smem (thread's r-cols == its h-feature cols)
        float hold[RPT][4], zz[RPT][4];
        #pragma unroll
        for (int i = 0; i < RPT; ++i)
            #pragma unroll
            for (int j = 0; j < 4; ++j) {
                hold[i][j] = h_s[(c4 + j) * TRP2 + 2 * (row0 + i)];
                zz[i][j] = sigmoidf_(fZ[i][j] + bgz[j]);
                float rr = sigmoidf_(fR[i][j] + bgr[j]);
                float rh = rr * hold[i][j];
                ull p;
                PACK2(p, rh, rh);
                *reinterpret_cast<ull*>(&rh_s[(c4 + j) * TRP2 + 2 * (row0 + i)]) = p;
            }
        __syncthreads();   // rh_s ready; all h_s reads done

        // candidate: [x | r*h] @ out_w^T  (cols 0..127)
        ull aC[RPT][2];
        ZERO6x2(aC);
        #pragma unroll 4
        for (int k = 0; k < H_; ++k) {
            ulonglong2 w0 = __ldg(reinterpret_cast<const ulonglong2*>(
                g_owT + (size_t)k * H_ + c4));
            const float* ap = x_s + k * TRP2 + row0d;
            ull a2[RPT];
            #pragma unroll
            for (int i = 0; i < RPT; ++i)
                a2[i] = *reinterpret_cast<const ull*>(ap + 2 * i);
            #pragma unroll
            for (int i = 0; i < RPT; ++i) {
                FMA2(aC[i][0], a2[i], w0.x, aC[i][0]);
                FMA2(aC[i][1], a2[i], w0.y, aC[i][1]);
            }
        }
        #pragma unroll 4
        for (int k = 0; k < H_; ++k) {
            ulonglong2 w0 = __ldg(reinterpret_cast<const ulonglong2*>(
                g_owT + (size_t)(H_ + k) * H_ + c4));
            const float* ap = rh_s + k * TRP2 + row0d;
            ull a2[RPT];
            #pragma unroll
            for (int i = 0; i < RPT; ++i)
                a2[i] = *reinterpret_cast<const ull*>(ap + 2 * i);
            #pragma unroll
            for (int i = 0; i < RPT; ++i) {
                FMA2(aC[i][0], a2[i], w0.x, aC[i][0]);
                FMA2(aC[i][1], a2[i], w0.y, aC[i][1]);
            }
        }

        float fC[RPT][4];
        UNPACK6x2(fC, aC);

        float hn[RPT][4];
        #pragma unroll
        for (int i = 0; i < RPT; ++i)
            #pragma unroll
            for (int j = 0; j < 4; ++j) {
                float cand = tanhf_(fC[i][j] + bo[j]);
                hn[i][j] = zz[i][j] * hold[i][j] + (1.f - zz[i][j]) * cand;
            }
        __syncthreads();   // all x_s / rh_s reads done before overwrites

        #pragma unroll
        for (int i = 0; i < RPT; ++i) {
            #pragma unroll
            for (int j = 0; j < 4; ++j) {
                ull p;
                PACK2(p, hn[i][j], hn[i][j]);
                *reinterpret_cast<ull*>(&h_s[(c4 + j) * TRP2 + 2 * (row0 + i)]) = p;
            }
            int bn = bn0 + row0 + i;
            if (bn < BN)
                *reinterpret_cast<float4*>(out + ((size_t)bn * T_ + t) * H_ + c4)
                    = make_float4(hn[i][0], hn[i][1], hn[i][2], hn[i][3]);
        }
    }
}

extern "C" void kernel_launch(void* const* d_in, const int* in_sizes, int n_in,
                              void* d_out, int out_size)
{
    const float* x      = (const float*)d_in[0];
    const float* w_ih   = (const float*)d_in[1];
    const float* w_hh   = (const float*)d_in[2];
    const float* b_ih   = (const float*)d_in[3];
    const float* b_hh   = (const float*)d_in[4];
    const float* gate_w = (const float*)d_in[5];
    const float* gate_b = (const float*)d_in[6];
    const float* out_w  = (const float*)d_in[7];
    const float* out_b  = (const float*)d_in[8];
    float* out = (float*)d_out;

    transpose_weights<<<(H2_ * H2_ + 255) / 256, 256>>>(w_ih, w_hh, gate_w, out_w);
    gru_layer0<<<NCTA, 256>>>(x, b_ih, b_hh);
    gru_layer1<<<NCTA, 256>>>(gate_b, out_b, out);
}

// round 7
// speedup vs baseline: 1.7802x; 1.7802x over previous
#include <cuda_runtime.h>
#include <math.h>

#define BN   20800
#define T_   24
#define F_   64
#define H_   128
#define TRR  48
#define NCTA 434          // ceil(20800/48)
#define NTH  512

typedef unsigned int uint32;

// ---------------- global scratch ----------------
// prepacked B-fragments (term 0=hi, 1=lo), float2 per (tile, lane)
__device__ float2 g_wihP[2 * 384  * 32];   // w_ih  [384x64]  : 48 nt x 8 kt
__device__ float2 g_whhP[2 * 768  * 32];   // w_hh  [384x128] : 48 nt x 16 kt
__device__ float2 g_gwP [2 * 1024 * 32];   // gate_w[256x256] : 32 nt x 32 kt
__device__ float2 g_owP [2 * 512  * 32];   // out_w [128x256] : 16 nt x 32 kt
__device__ float  g_seq1[(size_t)BN * T_ * H_];

// ---------------- helpers ----------------
__device__ __forceinline__ void tf32_split(float v, float& hi, float& lo) {
    uint32 b;
    asm("cvt.rna.tf32.f32 %0, %1;" : "=r"(b) : "f"(v));
    hi = __uint_as_float(b);
    float r = v - hi;
    asm("cvt.rna.tf32.f32 %0, %1;" : "=r"(b) : "f"(r));
    lo = __uint_as_float(b);
}

__device__ __forceinline__ float sigmoidf_(float v) {
    return __fdividef(1.0f, 1.0f + __expf(-v));
}
__device__ __forceinline__ float tanhf_(float v) {
    return __fdividef(2.0f, 1.0f + __expf(-2.0f * v)) - 1.0f;
}

// D += A * B, m16n8k8 tf32 (row.col). a: 4 b32 regs, b: 2 b32 regs.
__device__ __forceinline__ void mma8(float d[4], const uint32* a, float2 b) {
    asm volatile(
        "mma.sync.aligned.m16n8k8.row.col.f32.tf32.tf32.f32 "
        "{%0,%1,%2,%3},{%4,%5,%6,%7},{%8,%9},{%0,%1,%2,%3};"
        : "+f"(d[0]), "+f"(d[1]), "+f"(d[2]), "+f"(d[3])
        : "r"(a[0]), "r"(a[1]), "r"(a[2]), "r"(a[3]),
          "r"(__float_as_uint(b.x)), "r"(__float_as_uint(b.y)));
}

// write scalar element (m,k) into A-fragment-ordered smem array
// layout: [term][mt(3)][kt(KT)][lane(32)][reg(4)] floats
__device__ __forceinline__ void frag_write(float* base, int KT, int term,
                                           int mt, int kt, int m, int k, float v) {
    int lp = ((m & 7) << 2) | (k & 3);
    int rp = ((m >> 3) & 1) | (((k >> 2) & 1) << 1);
    base[(((term * 3 + mt) * KT + kt) * 32 + lp) * 4 + rp] = v;
}

// ---------------- weight prepack into B-fragment order ----------------
__global__ void prepack(const float* __restrict__ w_ih, const float* __restrict__ w_hh,
                        const float* __restrict__ gw,  const float* __restrict__ ow)
{
    int idx = blockIdx.x * blockDim.x + threadIdx.x;   // 2688 tiles * 32 lanes
    if (idx >= 2688 * 32) return;
    int lane = idx & 31, tile = idx >> 5;
    int g = lane >> 2, tig = lane & 3;
    const float* W; float2* dst; int TILES, ld, lt;
    if      (tile < 384)  { W = w_ih; dst = g_wihP; TILES = 384;  ld = 64;  lt = tile; }
    else if (tile < 1152) { W = w_hh; dst = g_whhP; TILES = 768;  ld = 128; lt = tile - 384; }
    else if (tile < 2176) { W = gw;   dst = g_gwP;  TILES = 1024; ld = 256; lt = tile - 1152; }
    else                  { W = ow;   dst = g_owP;  TILES = 512;  ld = 256; lt = tile - 2176; }
    int KT = ld >> 3;
    int n = (lt / KT) * 8 + g;            // output row
    int k = (lt % KT) * 8 + tig;          // input col
    float v0 = W[n * ld + k], v1 = W[n * ld + k + 4];
    float h0, l0, h1, l1;
    tf32_split(v0, h0, l0); tf32_split(v1, h1, l1);
    dst[(0 * TILES + lt) * 32 + lane] = make_float2(h0, h1);
    dst[(1 * TILES + lt) * 32 + lane] = make_float2(l0, l1);
}

// ---------------- Layer 0: torch GRUCell ----------------
__global__ __launch_bounds__(NTH, 1)
void gru_layer0(const float* __restrict__ x,
                const float* __restrict__ b_ih, const float* __restrict__ b_hh)
{
    extern __shared__ float sm[];
    float* xf = sm;                 // [2][3][8][32][4]  = 6144 floats
    float* hf = sm + 6144;          // [2][3][16][32][4] = 12288 floats
    const int tid = threadIdx.x;
    const int w = tid >> 5, lane = tid & 31;
    const int g = lane >> 2, tig = lane & 3;
    const int bn0 = blockIdx.x * TRR;

    for (int i = tid; i < 12288; i += NTH) hf[i] = 0.f;

    const int c0 = 8 * w + 2 * tig;                 // even output col owned
    float br0 = b_ih[c0]       + b_hh[c0],       br1 = b_ih[c0+1]     + b_hh[c0+1];
    float bz0 = b_ih[128 + c0] + b_hh[128 + c0], bz1 = b_ih[129 + c0] + b_hh[129 + c0];
    float bx0 = b_ih[256 + c0], bx1 = b_ih[257 + c0];
    float bh0 = b_hh[256 + c0], bh1 = b_hh[257 + c0];

    float hreg[3][4];
    #pragma unroll
    for (int mt = 0; mt < 3; ++mt)
        #pragma unroll
        for (int r = 0; r < 4; ++r) hreg[mt][r] = 0.f;

    for (int t = 0; t < T_; ++t) {
        // ---- x tile: 48x64, split + A-frag store ----
        #pragma unroll
        for (int i = 0; i < 6; ++i) {
            int idx = tid + i * NTH;            // 0..3071
            int row = idx >> 6, col = idx & 63;
            int bn = bn0 + row;
            float v = (bn < BN) ? x[((size_t)bn * T_ + t) * F_ + col] : 0.f;
            float hi, lo; tf32_split(v, hi, lo);
            frag_write(xf, 8, 0, row >> 4, col >> 3, row, col, hi);
            frag_write(xf, 8, 1, row >> 4, col >> 3, row, col, lo);
        }
        __syncthreads();

        float aR[3][4], aZ[3][4], aNX[3][4], aNH[3][4];
        #pragma unroll
        for (int mt = 0; mt < 3; ++mt) {
            aR[mt][0] = br0; aR[mt][1] = br1; aR[mt][2] = br0; aR[mt][3] = br1;
            aZ[mt][0] = bz0; aZ[mt][1] = bz1; aZ[mt][2] = bz0; aZ[mt][3] = bz1;
            aNX[mt][0] = bx0; aNX[mt][1] = bx1; aNX[mt][2] = bx0; aNX[mt][3] = bx1;
            aNH[mt][0] = bh0; aNH[mt][1] = bh1; aNH[mt][2] = bh0; aNH[mt][3] = bh1;
        }

        // ---- x-part GEMM: K=64 ----
        for (int kt = 0; kt < 8; ++kt) {
            uint4 ah[3], al[3];
            #pragma unroll
            for (int mt = 0; mt < 3; ++mt) {
                ah[mt] = ((const uint4*)xf)[((0 * 3 + mt) * 8 + kt) * 32 + lane];
                al[mt] = ((const uint4*)xf)[((1 * 3 + mt) * 8 + kt) * 32 + lane];
            }
            float2 bRh = g_wihP[(0 * 384 + (     w) * 8 + kt) * 32 + lane];
            float2 bRl = g_wihP[(1 * 384 + (     w) * 8 + kt) * 32 + lane];
            float2 bZh = g_wihP[(0 * 384 + (16 + w) * 8 + kt) * 32 + lane];
            float2 bZl = g_wihP[(1 * 384 + (16 + w) * 8 + kt) * 32 + lane];
            float2 bNh = g_wihP[(0 * 384 + (32 + w) * 8 + kt) * 32 + lane];
            float2 bNl = g_wihP[(1 * 384 + (32 + w) * 8 + kt) * 32 + lane];
            #pragma unroll
            for (int mt = 0; mt < 3; ++mt) {
                const uint32* AH = (const uint32*)&ah[mt];
                const uint32* AL = (const uint32*)&al[mt];
                mma8(aR[mt],  AH, bRh); mma8(aR[mt],  AL, bRh); mma8(aR[mt],  AH, bRl);
                mma8(aZ[mt],  AH, bZh); mma8(aZ[mt],  AL, bZh); mma8(aZ[mt],  AH, bZl);
                mma8(aNX[mt], AH, bNh); mma8(aNX[mt], AL, bNh); mma8(aNX[mt], AH, bNl);
            }
        }
        // ---- h-part GEMM: K=128 (n-gate accumulates separately into aNH) ----
        for (int kt = 0; kt < 16; ++kt) {
            uint4 ah[3], al[3];
            #pragma unroll
            for (int mt = 0; mt < 3; ++mt) {
                ah[mt] = ((const uint4*)hf)[((0 * 3 + mt) * 16 + kt) * 32 + lane];
                al[mt] = ((const uint4*)hf)[((1 * 3 + mt) * 16 + kt) * 32 + lane];
            }
            float2 bRh = g_whhP[(0 * 768 + (     w) * 16 + kt) * 32 + lane];
            float2 bRl = g_whhP[(1 * 768 + (     w) * 16 + kt) * 32 + lane];
            float2 bZh = g_whhP[(0 * 768 + (16 + w) * 16 + kt) * 32 + lane];
            float2 bZl = g_whhP[(1 * 768 + (16 + w) * 16 + kt) * 32 + lane];
            float2 bNh = g_whhP[(0 * 768 + (32 + w) * 16 + kt) * 32 + lane];
            float2 bNl = g_whhP[(1 * 768 + (32 + w) * 16 + kt) * 32 + lane];
            #pragma unroll
            for (int mt = 0; mt < 3; ++mt) {
                const uint32* AH = (const uint32*)&ah[mt];
                const uint32* AL = (const uint32*)&al[mt];
                mma8(aR[mt],  AH, bRh); mma8(aR[mt],  AL, bRh); mma8(aR[mt],  AH, bRl);
                mma8(aZ[mt],  AH, bZh); mma8(aZ[mt],  AL, bZh); mma8(aZ[mt],  AH, bZl);
                mma8(aNH[mt], AH, bNh); mma8(aNH[mt], AL, bNh); mma8(aNH[mt], AH, bNl);
            }
        }
        __syncthreads();   // all MMA reads of hf/xf done

        // ---- epilogue: gates + h update (warp-local cols [8w, 8w+8)) ----
        #pragma unroll
        for (int mt = 0; mt < 3; ++mt)
            #pragma unroll
            for (int r = 0; r < 4; ++r) {
                int m   = mt * 16 + g + 8 * (r >> 1);
                int col = c0 + (r & 1);
                float rr = sigmoidf_(aR[mt][r]);
                float zz = sigmoidf_(aZ[mt][r]);
                float n  = tanhf_(aNX[mt][r] + rr * aNH[mt][r]);
                float hn = (1.f - zz) * n + zz * hreg[mt][r];
                hreg[mt][r] = hn;
                float hi, lo; tf32_split(hn, hi, lo);
                frag_write(hf, 16, 0, mt, col >> 3, m, col, hi);
                frag_write(hf, 16, 1, mt, col >> 3, m, col, lo);
                int bn = bn0 + m;
                if (bn < BN)
                    g_seq1[((size_t)bn * T_ + t) * H_ + col] = hn;
            }
        // next-iter __syncthreads orders hf writes vs. next MMA reads
    }
}

// ---------------- Layer 1: custom GRUCell ----------------
__global__ __launch_bounds__(NTH, 1)
void gru_layer1(const float* __restrict__ gate_b, const float* __restrict__ out_b,
                float* __restrict__ out)
{
    extern __shared__ float sm[];
    float* xf = sm;                  // [2][3][16][32][4] = 12288 floats
    float* hf = sm + 12288;          // h frags, later overwritten by r*h frags
    const int tid = threadIdx.x;
    const int w = tid >> 5, lane = tid & 31;
    const int g = lane >> 2, tig = lane & 3;
    const int bn0 = blockIdx.x * TRR;

    for (int i = tid; i < 12288; i += NTH) hf[i] = 0.f;

    const int c0 = 8 * w + 2 * tig;
    float bgr0 = gate_b[c0],       bgr1 = gate_b[c0 + 1];
    float bgz0 = gate_b[128 + c0], bgz1 = gate_b[129 + c0];
    float bo0  = out_b[c0],        bo1  = out_b[c0 + 1];

    float hreg[3][4];
    #pragma unroll
    for (int mt = 0; mt < 3; ++mt)
        #pragma unroll
        for (int r = 0; r < 4; ++r) hreg[mt][r] = 0.f;

    for (int t = 0; t < T_; ++t) {
        // ---- x tile: 48x128 from g_seq1 ----
        #pragma unroll
        for (int i = 0; i < 12; ++i) {
            int idx = tid + i * NTH;             // 0..6143
            int row = idx >> 7, col = idx & 127;
            int bn = bn0 + row;
            float v = (bn < BN) ? g_seq1[((size_t)bn * T_ + t) * H_ + col] : 0.f;
            float hi, lo; tf32_split(v, hi, lo);
            frag_write(xf, 16, 0, row >> 4, col >> 3, row, col, hi);
            frag_write(xf, 16, 1, row >> 4, col >> 3, row, col, lo);
        }
        __syncthreads();   // S1: xf ready, hf (from prev epi2) ready

        // ---- gates GEMM: r,z over K=256 ----
        float aR[3][4], aZ[3][4];
        #pragma unroll
        for (int mt = 0; mt < 3; ++mt) {
            aR[mt][0] = bgr0; aR[mt][1] = bgr1; aR[mt][2] = bgr0; aR[mt][3] = bgr1;
            aZ[mt][0] = bgz0; aZ[mt][1] = bgz1; aZ[mt][2] = bgz0; aZ[mt][3] = bgz1;
        }
        for (int kt = 0; kt < 16; ++kt) {        // x half (gate_w cols 0..127)
            uint4 ah[3], al[3];
            #pragma unroll
            for (int mt = 0; mt < 3; ++mt) {
                ah[mt] = ((const uint4*)xf)[((0 * 3 + mt) * 16 + kt) * 32 + lane];
                al[mt] = ((const uint4*)xf)[((1 * 3 + mt) * 16 + kt) * 32 + lane];
            }
            float2 bRh = g_gwP[(0 * 1024 + (     w) * 32 + kt) * 32 + lane];
            float2 bRl = g_gwP[(1 * 1024 + (     w) * 32 + kt) * 32 + lane];
            float2 bZh = g_gwP[(0 * 1024 + (16 + w) * 32 + kt) * 32 + lane];
            float2 bZl = g_gwP[(1 * 1024 + (16 + w) * 32 + kt) * 32 + lane];
            #pragma unroll
            for (int mt = 0; mt < 3; ++mt) {
                const uint32* AH = (const uint32*)&ah[mt];
                const uint32* AL = (const uint32*)&al[mt];
                mma8(aR[mt], AH, bRh); mma8(aR[mt], AL, bRh); mma8(aR[mt], AH, bRl);
                mma8(aZ[mt], AH, bZh); mma8(aZ[mt], AL, bZh); mma8(aZ[mt], AH, bZl);
            }
        }
        for (int kt = 0; kt < 16; ++kt) {        // h half (gate_w cols 128..255)
            uint4 ah[3], al[3];
            #pragma unroll
            for (int mt = 0; mt < 3; ++mt) {
                ah[mt] = ((const uint4*)hf)[((0 * 3 + mt) * 16 + kt) * 32 + lane];
                al[mt] = ((const uint4*)hf)[((1 * 3 + mt) * 16 + kt) * 32 + lane];
            }
            float2 bRh = g_gwP[(0 * 1024 + (     w) * 32 + 16 + kt) * 32 + lane];
            float2 bRl = g_gwP[(1 * 1024 + (     w) * 32 + 16 + kt) * 32 + lane];
            float2 bZh = g_gwP[(0 * 1024 + (16 + w) * 32 + 16 + kt) * 32 + lane];
            float2 bZl = g_gwP[(1 * 1024 + (16 + w) * 32 + 16 + kt) * 32 + lane];
            #pragma unroll
            for (int mt = 0; mt < 3; ++mt) {
                const uint32* AH = (const uint32*)&ah[mt];
                const uint32* AL = (const uint32*)&al[mt];
                mma8(aR[mt], AH, bRh); mma8(aR[mt], AL, bRh); mma8(aR[mt], AH, bRl);
                mma8(aZ[mt], AH, bZh); mma8(aZ[mt], AL, bZh); mma8(aZ[mt], AH, bZl);
            }
        }
        __syncthreads();   // S2: gate MMA reads of hf done — safe to overwrite

        // ---- epilogue 1: r,z ; write r*h frags into hf ----
        float zz[3][4], hold[3][4];
        #pragma unroll
        for (int mt = 0; mt < 3; ++mt)
            #pragma unroll
            for (int r = 0; r < 4; ++r) {
                int m   = mt * 16 + g + 8 * (r >> 1);
                int col = c0 + (r & 1);
                float rr = sigmoidf_(aR[mt][r]);
                zz[mt][r]   = sigmoidf_(aZ[mt][r]);
                hold[mt][r] = hreg[mt][r];
                float rh = rr * hold[mt][r];
                float hi, lo; tf32_split(rh, hi, lo);
                frag_write(hf, 16, 0, mt, col >> 3, m, col, hi);
                frag_write(hf, 16, 1, mt, col >> 3, m, col, lo);
            }
        __syncthreads();   // S3: rh frags visible to all

        // ---- candidate GEMM: [x | r*h] @ out_w^T, K=256 ----
        float aC[3][4];
        #pragma unroll
        for (int mt = 0; mt < 3; ++mt) {
            aC[mt][0] = bo0; aC[mt][1] = bo1; aC[mt][2] = bo0; aC[mt][3] = bo1;
        }
        for (int kt = 0; kt < 16; ++kt) {        // x half
            uint4 ah[3], al[3];
            #pragma unroll
            for (int mt = 0; mt < 3; ++mt) {
                ah[mt] = ((const uint4*)xf)[((0 * 3 + mt) * 16 + kt) * 32 + lane];
                al[mt] = ((const uint4*)xf)[((1 * 3 + mt) * 16 + kt) * 32 + lane];
            }
            float2 bh = g_owP[(0 * 512 + w * 32 + kt) * 32 + lane];
            float2 bl = g_owP[(1 * 512 + w * 32 + kt) * 32 + lane];
            #pragma unroll
            for (int mt = 0; mt < 3; ++mt) {
                const uint32* AH = (const uint32*)&ah[mt];
                const uint32* AL = (const uint32*)&al[mt];
                mma8(aC[mt], AH, bh); mma8(aC[mt], AL, bh); mma8(aC[mt], AH, bl);
            }
        }
        for (int kt = 0; kt < 16; ++kt) {        // r*h half
            uint4 ah[3], al[3];
            #pragma unroll
            for (int mt = 0; mt < 3; ++mt) {
                ah[mt] = ((const uint4*)hf)[((0 * 3 + mt) * 16 + kt) * 32 + lane];
                al[mt] = ((const uint4*)hf)[((1 * 3 + mt) * 16 + kt) * 32 + lane];
            }
            float2 bh = g_owP[(0 * 512 + w * 32 + 16 + kt) * 32 + lane];
            float2 bl = g_owP[(1 * 512 + w * 32 + 16 + kt) * 32 + lane];
            #pragma unroll
            for (int mt = 0; mt < 3; ++mt) {
                const uint32* AH = (const uint32*)&ah[mt];
                const uint32* AL = (const uint32*)&al[mt];
                mma8(aC[mt], AH, bh); mma8(aC[mt], AL, bh); mma8(aC[mt], AH, bl);
            }
        }
        __syncthreads();   // S4: cand MMA reads of hf done — safe to overwrite

        // ---- epilogue 2: h update ----
        #pragma unroll
        for (int mt = 0; mt < 3; ++mt)
            #pragma unroll
            for (int r = 0; r < 4; ++r) {
                int m   = mt * 16 + g + 8 * (r >> 1);
                int col = c0 + (r & 1);
                float cand = tanhf_(aC[mt][r]);
                float hn = zz[mt][r] * hold[mt][r] + (1.f - zz[mt][r]) * cand;
                hreg[mt][r] = hn;
                float hi, lo; tf32_split(hn, hi, lo);
                frag_write(hf, 16, 0, mt, col >> 3, m, col, hi);
                frag_write(hf, 16, 1, mt, col >> 3, m, col, lo);
                int bn = bn0 + m;
                if (bn < BN)
                    out[((size_t)bn * T_ + t) * H_ + col] = hn;
            }
        // next-iter S1 orders hf writes vs. next gate MMA reads
    }
}

extern "C" void kernel_launch(void* const* d_in, const int* in_sizes, int n_in,
                              void* d_out, int out_size)
{
    const float* x      = (const float*)d_in[0];
    const float* w_ih   = (const float*)d_in[1];
    const float* w_hh   = (const float*)d_in[2];
    const float* b_ih   = (const float*)d_in[3];
    const float* b_hh   = (const float*)d_in[4];
    const float* gate_w = (const float*)d_in[5];
    const float* gate_b = (const float*)d_in[6];
    const float* out_w  = (const float*)d_in[7];
    const float* out_b  = (const float*)d_in[8];
    float* out = (float*)d_out;

    const int smem0 = (6144 + 12288) * 4;    // 73728 B
    const int smem1 = (12288 + 12288) * 4;   // 98304 B
    cudaFuncSetAttribute(gru_layer0, cudaFuncAttributeMaxDynamicSharedMemorySize, smem0);
    cudaFuncSetAttribute(gru_layer1, cudaFuncAttributeMaxDynamicSharedMemorySize, smem1);

    prepack<<<168, 512>>>(w_ih, w_hh, gate_w, out_w);
    gru_layer0<<<NCTA, NTH, smem0>>>(x, b_ih, b_hh);
    gru_layer1<<<NCTA, NTH, smem1>>>(gate_b, out_b, out);
}

// round 9
// speedup vs baseline: 1.9659x; 1.1043x over previous
#include <cuda_runtime.h>
#include <math.h>

#define BN   20800
#define T_   24
#define F_   64
#define H_   128
#define TRR  48
#define NCTA 434          // ceil(20800/48)
#define NTH  512

typedef unsigned int uint32;

// ---------------- global scratch ----------------
// prepacked B-fragments (term 0=hi, 1=lo), float2 per (tile, lane)  [tf32 m16n8k8]
__device__ float2 g_wihP[2 * 384  * 32];   // w_ih  [384x64]  : 48 nt x 8 kt
__device__ float2 g_whhP[2 * 768  * 32];   // w_hh  [384x128] : 48 nt x 16 kt
__device__ float2 g_gwP [2 * 1024 * 32];   // gate_w[256x256] : 32 nt x 32 kt
__device__ float2 g_owP [2 * 512  * 32];   // out_w [128x256] : 16 nt x 32 kt

// ---------------- helpers ----------------
__device__ __forceinline__ void tf32_split(float v, float& hi, float& lo) {
    uint32 b;
    asm("cvt.rna.tf32.f32 %0, %1;" : "=r"(b) : "f"(v));
    hi = __uint_as_float(b);
    float r = v - hi;
    asm("cvt.rna.tf32.f32 %0, %1;" : "=r"(b) : "f"(r));
    lo = __uint_as_float(b);
}

__device__ __forceinline__ float sigmoidf_(float v) {
    return __fdividef(1.0f, 1.0f + __expf(-v));
}
__device__ __forceinline__ float tanhf_(float v) {
    return __fdividef(2.0f, 1.0f + __expf(-2.0f * v)) - 1.0f;
}

// D += A * B, m16n8k8 tf32 (row.col). a: 4 b32 regs, b: 2 b32 regs.
__device__ __forceinline__ void mma8(float d[4], const uint32* a, float2 b) {
    asm volatile(
        "mma.sync.aligned.m16n8k8.row.col.f32.tf32.tf32.f32 "
        "{%0,%1,%2,%3},{%4,%5,%6,%7},{%8,%9},{%0,%1,%2,%3};"
        : "+f"(d[0]), "+f"(d[1]), "+f"(d[2]), "+f"(d[3])
        : "r"(a[0]), "r"(a[1]), "r"(a[2]), "r"(a[3]),
          "r"(__float_as_uint(b.x)), "r"(__float_as_uint(b.y)));
}

// write scalar element (m,k) into A-fragment-ordered smem array
// layout: [term][mt(3)][kt(KT)][lane(32)][reg(4)] floats
__device__ __forceinline__ void frag_write(float* base, int KT, int term,
                                           int mt, int kt, int m, int k, float v) {
    int lp = ((m & 7) << 2) | (k & 3);
    int rp = ((m >> 3) & 1) | (((k >> 2) & 1) << 1);
    base[(((term * 3 + mt) * KT + kt) * 32 + lp) * 4 + rp] = v;
}

// read back element (m,k) as hi + lo (tf32-split representation, ~2^-21 exact)
__device__ __forceinline__ float frag_read2(const float* base, int KT,
                                            int mt, int kt, int m, int k) {
    int lp = ((m & 7) << 2) | (k & 3);
    int rp = ((m >> 3) & 1) | (((k >> 2) & 1) << 1);
    return base[(((0 * 3 + mt) * KT + kt) * 32 + lp) * 4 + rp]
         + base[(((1 * 3 + mt) * KT + kt) * 32 + lp) * 4 + rp];
}

// ---------------- weight prepack into B-fragment order ----------------
__global__ void prepack(const float* __restrict__ w_ih, const float* __restrict__ w_hh,
                        const float* __restrict__ gw,  const float* __restrict__ ow)
{
    int idx = blockIdx.x * blockDim.x + threadIdx.x;   // 2688 tiles * 32 lanes
    if (idx >= 2688 * 32) return;
    int lane = idx & 31, tile = idx >> 5;
    int g = lane >> 2, tig = lane & 3;
    const float* W; float2* dst; int TILES, ld, lt;
    if      (tile < 384)  { W = w_ih; dst = g_wihP; TILES = 384;  ld = 64;  lt = tile; }
    else if (tile < 1152) { W = w_hh; dst = g_whhP; TILES = 768;  ld = 128; lt = tile - 384; }
    else if (tile < 2176) { W = gw;   dst = g_gwP;  TILES = 1024; ld = 256; lt = tile - 1152; }
    else                  { W = ow;   dst = g_owP;  TILES = 512;  ld = 256; lt = tile - 2176; }
    int KT = ld >> 3;
    int n = (lt / KT) * 8 + g;            // output row
    int k = (lt % KT) * 8 + tig;          // input col
    float v0 = W[n * ld + k], v1 = W[n * ld + k + 4];
    float h0, l0, h1, l1;
    tf32_split(v0, h0, l0); tf32_split(v1, h1, l1);
    dst[(0 * TILES + lt) * 32 + lane] = make_float2(h0, h1);
    dst[(1 * TILES + lt) * 32 + lane] = make_float2(l0, l1);
}

// ---------------- Fused 2-layer GRU over T steps ----------------
// Per CTA: 48 sequences. Both recurrences advance together per t; layer0's
// h frags feed layer1 directly (no gmem round-trip).
__global__ __launch_bounds__(NTH, 1)
void gru_fused(const float* __restrict__ x,
               const float* __restrict__ b_ih, const float* __restrict__ b_hh,
               const float* __restrict__ gate_b, const float* __restrict__ out_b,
               float* __restrict__ out)
{
    extern __shared__ float sm[];
    float* xf  = sm;            // [2][3][8][32][4]  = 6144  (x tile, KT=8)
    float* h0f = sm + 6144;     // [2][3][16][32][4] = 12288 (layer0 h, KT=16)
    float* h1f = sm + 18432;    // 12288 (layer1 h)
    float* rhf = sm + 30720;    // 12288 (r * h1)
    const int tid = threadIdx.x;
    const int w = tid >> 5, lane = tid & 31;
    const int g = lane >> 2, tig = lane & 3;
    const int bn0 = blockIdx.x * TRR;

    // zero h0f + h1f (contiguous 24576 floats)
    for (int i = tid; i < 24576; i += NTH) h0f[i] = 0.f;

    const int c0 = 8 * w + 2 * tig;
    // layer0 biases
    float br0 = b_ih[c0]       + b_hh[c0],       br1 = b_ih[c0+1]     + b_hh[c0+1];
    float bz0 = b_ih[128 + c0] + b_hh[128 + c0], bz1 = b_ih[129 + c0] + b_hh[129 + c0];
    float bx0 = b_ih[256 + c0], bx1 = b_ih[257 + c0];
    float bh0 = b_hh[256 + c0], bh1 = b_hh[257 + c0];
    // layer1 biases
    float bgr0 = gate_b[c0],       bgr1 = gate_b[c0 + 1];
    float bgz0 = gate_b[128 + c0], bgz1 = gate_b[129 + c0];
    float bo0  = out_b[c0],        bo1  = out_b[c0 + 1];

    for (int t = 0; t < T_; ++t) {
        // ==== stage x(t): 48x64, tf32 split + A-frag store ====
        #pragma unroll
        for (int i = 0; i < 6; ++i) {
            int idx = tid + i * NTH;            // 0..3071
            int row = idx >> 6, col = idx & 63;
            int bn = bn0 + row;
            float v = (bn < BN) ? x[((size_t)bn * T_ + t) * F_ + col] : 0.f;
            float hi, lo; tf32_split(v, hi, lo);
            frag_write(xf, 8, 0, row >> 4, col >> 3, row, col, hi);
            frag_write(xf, 8, 1, row >> 4, col >> 3, row, col, lo);
        }
        __syncthreads();   // S1: xf ready; h0f/h1f from prev step ready

        // ==== layer0 GEMMs ====
        float aR[3][4], aZ[3][4], aNX[3][4], aNH[3][4];
        #pragma unroll
        for (int mt = 0; mt < 3; ++mt) {
            aR[mt][0] = br0; aR[mt][1] = br1; aR[mt][2] = br0; aR[mt][3] = br1;
            aZ[mt][0] = bz0; aZ[mt][1] = bz1; aZ[mt][2] = bz0; aZ[mt][3] = bz1;
            aNX[mt][0] = bx0; aNX[mt][1] = bx1; aNX[mt][2] = bx0; aNX[mt][3] = bx1;
            aNH[mt][0] = bh0; aNH[mt][1] = bh1; aNH[mt][2] = bh0; aNH[mt][3] = bh1;
        }
        for (int kt = 0; kt < 8; ++kt) {        // x-part, K=64
            uint4 ah[3], al[3];
            #pragma unroll
            for (int mt = 0; mt < 3; ++mt) {
                ah[mt] = ((const uint4*)xf)[((0 * 3 + mt) * 8 + kt) * 32 + lane];
                al[mt] = ((const uint4*)xf)[((1 * 3 + mt) * 8 + kt) * 32 + lane];
            }
            float2 bRh = g_wihP[(0 * 384 + (     w) * 8 + kt) * 32 + lane];
            float2 bRl = g_wihP[(1 * 384 + (     w) * 8 + kt) * 32 + lane];
            float2 bZh = g_wihP[(0 * 384 + (16 + w) * 8 + kt) * 32 + lane];
            float2 bZl = g_wihP[(1 * 384 + (16 + w) * 8 + kt) * 32 + lane];
            float2 bNh = g_wihP[(0 * 384 + (32 + w) * 8 + kt) * 32 + lane];
            float2 bNl = g_wihP[(1 * 384 + (32 + w) * 8 + kt) * 32 + lane];
            #pragma unroll
            for (int mt = 0; mt < 3; ++mt) {
                const uint32* AH = (const uint32*)&ah[mt];
                const uint32* AL = (const uint32*)&al[mt];
                mma8(aR[mt],  AH, bRh); mma8(aR[mt],  AL, bRh); mma8(aR[mt],  AH, bRl);
                mma8(aZ[mt],  AH, bZh); mma8(aZ[mt],  AL, bZh); mma8(aZ[mt],  AH, bZl);
                mma8(aNX[mt], AH, bNh); mma8(aNX[mt], AL, bNh); mma8(aNX[mt], AH, bNl);
            }
        }
        for (int kt = 0; kt < 16; ++kt) {       // h-part, K=128 (n gate into aNH)
            uint4 ah[3], al[3];
            #pragma unroll
            for (int mt = 0; mt < 3; ++mt) {
                ah[mt] = ((const uint4*)h0f)[((0 * 3 + mt) * 16 + kt) * 32 + lane];
                al[mt] = ((const uint4*)h0f)[((1 * 3 + mt) * 16 + kt) * 32 + lane];
            }
            float2 bRh = g_whhP[(0 * 768 + (     w) * 16 + kt) * 32 + lane];
            float2 bRl = g_whhP[(1 * 768 + (     w) * 16 + kt) * 32 + lane];
            float2 bZh = g_whhP[(0 * 768 + (16 + w) * 16 + kt) * 32 + lane];
            float2 bZl = g_whhP[(1 * 768 + (16 + w) * 16 + kt) * 32 + lane];
            float2 bNh = g_whhP[(0 * 768 + (32 + w) * 16 + kt) * 32 + lane];
            float2 bNl = g_whhP[(1 * 768 + (32 + w) * 16 + kt) * 32 + lane];
            #pragma unroll
            for (int mt = 0; mt < 3; ++mt) {
                const uint32* AH = (const uint32*)&ah[mt];
                const uint32* AL = (const uint32*)&al[mt];
                mma8(aR[mt],  AH, bRh); mma8(aR[mt],  AL, bRh); mma8(aR[mt],  AH, bRl);
                mma8(aZ[mt],  AH, bZh); mma8(aZ[mt],  AL, bZh); mma8(aZ[mt],  AH, bZl);
                mma8(aNH[mt], AH, bNh); mma8(aNH[mt], AL, bNh); mma8(aNH[mt], AH, bNl);
            }
        }
        __syncthreads();   // S2: all reads of h0f (and xf) done

        // ==== layer0 epilogue: h0(t) -> h0f (also layer1's x input) ====
        #pragma unroll
        for (int mt = 0; mt < 3; ++mt)
            #pragma unroll
            for (int r = 0; r < 4; ++r) {
                int m   = mt * 16 + g + 8 * (r >> 1);
                int col = c0 + (r & 1);
                float hold = frag_read2(h0f, 16, mt, col >> 3, m, col);
                float rr = sigmoidf_(aR[mt][r]);
                float zz = sigmoidf_(aZ[mt][r]);
                float n  = tanhf_(aNX[mt][r] + rr * aNH[mt][r]);
                float hn = (1.f - zz) * n + zz * hold;
                float hi, lo; tf32_split(hn, hi, lo);
                frag_write(h0f, 16, 0, mt, col >> 3, m, col, hi);
                frag_write(h0f, 16, 1, mt, col >> 3, m, col, lo);
            }
        __syncthreads();   // S3: h0f(t) ready for layer1

        // ==== layer1 gates GEMM (+ candidate x-half, r-independent) ====
        float aR1[3][4], aZ1[3][4], aC[3][4];
        #pragma unroll
        for (int mt = 0; mt < 3; ++mt) {
            aR1[mt][0] = bgr0; aR1[mt][1] = bgr1; aR1[mt][2] = bgr0; aR1[mt][3] = bgr1;
            aZ1[mt][0] = bgz0; aZ1[mt][1] = bgz1; aZ1[mt][2] = bgz0; aZ1[mt][3] = bgz1;
            aC[mt][0]  = bo0;  aC[mt][1]  = bo1;  aC[mt][2]  = bo0;  aC[mt][3]  = bo1;
        }
        for (int kt = 0; kt < 16; ++kt) {       // x half: A = h0f, B = gw/ow cols 0..127
            uint4 ah[3], al[3];
            #pragma unroll
            for (int mt = 0; mt < 3; ++mt) {
                ah[mt] = ((const uint4*)h0f)[((0 * 3 + mt) * 16 + kt) * 32 + lane];
                al[mt] = ((const uint4*)h0f)[((1 * 3 + mt) * 16 + kt) * 32 + lane];
            }
            float2 bRh = g_gwP[(0 * 1024 + (     w) * 32 + kt) * 32 + lane];
            float2 bRl = g_gwP[(1 * 1024 + (     w) * 32 + kt) * 32 + lane];
            float2 bZh = g_gwP[(0 * 1024 + (16 + w) * 32 + kt) * 32 + lane];
            float2 bZl = g_gwP[(1 * 1024 + (16 + w) * 32 + kt) * 32 + lane];
            float2 bCh = g_owP[(0 * 512  +       w  * 32 + kt) * 32 + lane];
            float2 bCl = g_owP[(1 * 512  +       w  * 32 + kt) * 32 + lane];
            #pragma unroll
            for (int mt = 0; mt < 3; ++mt) {
                const uint32* AH = (const uint32*)&ah[mt];
                const uint32* AL = (const uint32*)&al[mt];
                mma8(aR1[mt], AH, bRh); mma8(aR1[mt], AL, bRh); mma8(aR1[mt], AH, bRl);
                mma8(aZ1[mt], AH, bZh); mma8(aZ1[mt], AL, bZh); mma8(aZ1[mt], AH, bZl);
                mma8(aC[mt],  AH, bCh); mma8(aC[mt],  AL, bCh); mma8(aC[mt],  AH, bCl);
            }
        }
        for (int kt = 0; kt < 16; ++kt) {       // h half: A = h1f, gates only
            uint4 ah[3], al[3];
            #pragma unroll
            for (int mt = 0; mt < 3; ++mt) {
                ah[mt] = ((const uint4*)h1f)[((0 * 3 + mt) * 16 + kt) * 32 + lane];
                al[mt] = ((const uint4*)h1f)[((1 * 3 + mt) * 16 + kt) * 32 + lane];
            }
            float2 bRh = g_gwP[(0 * 1024 + (     w) * 32 + 16 + kt) * 32 + lane];
            float2 bRl = g_gwP[(1 * 1024 + (     w) * 32 + 16 + kt) * 32 + lane];
            float2 bZh = g_gwP[(0 * 1024 + (16 + w) * 32 + 16 + kt) * 32 + lane];
            float2 bZl = g_gwP[(1 * 1024 + (16 + w) * 32 + 16 + kt) * 32 + lane];
            #pragma unroll
            for (int mt = 0; mt < 3; ++mt) {
                const uint32* AH = (const uint32*)&ah[mt];
                const uint32* AL = (const uint32*)&al[mt];
                mma8(aR1[mt], AH, bRh); mma8(aR1[mt], AL, bRh); mma8(aR1[mt], AH, bRl);
                mma8(aZ1[mt], AH, bZh); mma8(aZ1[mt], AL, bZh); mma8(aZ1[mt], AH, bZl);
            }
        }
        __syncthreads();   // S4: all reads of h1f done

        // ==== layer1 epilogue 1: r,z ; write r*h1 frags ====
        float zz1[3][4], hold1[3][4];
        #pragma unroll
        for (int mt = 0; mt < 3; ++mt)
            #pragma unroll
            for (int r = 0; r < 4; ++r) {
                int m   = mt * 16 + g + 8 * (r >> 1);
                int col = c0 + (r & 1);
                hold1[mt][r] = frag_read2(h1f, 16, mt, col >> 3, m, col);
                float rr = sigmoidf_(aR1[mt][r]);
                zz1[mt][r] = sigmoidf_(aZ1[mt][r]);
                float rh = rr * hold1[mt][r];
                float hi, lo; tf32_split(rh, hi, lo);
                frag_write(rhf, 16, 0, mt, col >> 3, m, col, hi);
                frag_write(rhf, 16, 1, mt, col >> 3, m, col, lo);
            }
        __syncthreads();   // S5: rhf ready

        // ==== candidate r*h half ====
        for (int kt = 0; kt < 16; ++kt) {
            uint4 ah[3], al[3];
            #pragma unroll
            for (int mt = 0; mt < 3; ++mt) {
                ah[mt] = ((const uint4*)rhf)[((0 * 3 + mt) * 16 + kt) * 32 + lane];
                al[mt] = ((const uint4*)rhf)[((1 * 3 + mt) * 16 + kt) * 32 + lane];
            }
            float2 bh = g_owP[(0 * 512 + w * 32 + 16 + kt) * 32 + lane];
            float2 bl = g_owP[(1 * 512 + w * 32 + 16 + kt) * 32 + lane];
            #pragma unroll
            for (int mt = 0; mt < 3; ++mt) {
                const uint32* AH = (const uint32*)&ah[mt];
                const uint32* AL = (const uint32*)&al[mt];
                mma8(aC[mt], AH, bh); mma8(aC[mt], AL, bh); mma8(aC[mt], AH, bl);
            }
        }

        // ==== layer1 epilogue 2: h1(t) -> h1f + gmem out ====
        // (no sync needed: h1f writes race nothing — gates-GEMM h1f reads ended
        //  at S4; other warps still in cand GEMM read only rhf/h0f)
        #pragma unroll
        for (int mt = 0; mt < 3; ++mt)
            #pragma unroll
            for (int r = 0; r < 4; ++r) {
                int m   = mt * 16 + g + 8 * (r >> 1);
                int col = c0 + (r & 1);
                float cand = tanhf_(aC[mt][r]);
                float hn = zz1[mt][r] * hold1[mt][r] + (1.f - zz1[mt][r]) * cand;
                float hi, lo; tf32_split(hn, hi, lo);
                frag_write(h1f, 16, 0, mt, col >> 3, m, col, hi);
                frag_write(h1f, 16, 1, mt, col >> 3, m, col, lo);
                int bn = bn0 + m;
                if (bn < BN)
                    out[((size_t)bn * T_ + t) * H_ + col] = hn;
            }
        // next-iter S1 orders h1f/h0f writes vs. next GEMM reads;
        // xf(t+1) writes are safe: xf reads ended at S2(t).
    }
}

extern "C" void kernel_launch(void* const* d_in, const int* in_sizes, int n_in,
                              void* d_out, int out_size)
{
    const float* x      = (const float*)d_in[0];
    const float* w_ih   = (const float*)d_in[1];
    const float* w_hh   = (const float*)d_in[2];
    const float* b_ih   = (const float*)d_in[3];
    const float* b_hh   = (const float*)d_in[4];
    const float* gate_w = (const float*)d_in[5];
    const float* gate_b = (const float*)d_in[6];
    const float* out_w  = (const float*)d_in[7];
    const float* out_b  = (const float*)d_in[8];
    float* out = (float*)d_out;

    const int smem = (6144 + 3 * 12288) * 4;   // 172032 B
    cudaFuncSetAttribute(gru_fused, cudaFuncAttributeMaxDynamicSharedMemorySize, smem);

    prepack<<<168, 512>>>(w_ih, w_hh, gate_w, out_w);
    gru_fused<<<NCTA, NTH, smem>>>(x, b_ih, b_hh, gate_b, out_b, out);
}

// round 10
// speedup vs baseline: 2.7387x; 1.3931x over previous
#include <cuda_runtime.h>
#include <math.h>

#define BN   20800
#define T_   24
#define F_   64
#define H_   128
#define TRR  48
#define NCTA 434          // ceil(20800/48)
#define NTH  512

typedef unsigned int uint32;

// ---------------- global scratch ----------------
// prepacked B-fragments (tf32 hi term only), float2 per (tile, lane)  [m16n8k8]
__device__ float2 g_wihP[384  * 32];   // w_ih  [384x64]  : 48 nt x 8 kt
__device__ float2 g_whhP[768  * 32];   // w_hh  [384x128] : 48 nt x 16 kt
__device__ float2 g_gwP [1024 * 32];   // gate_w[256x256] : 32 nt x 32 kt
__device__ float2 g_owP [512  * 32];   // out_w [128x256] : 16 nt x 32 kt

// ---------------- helpers ----------------
__device__ __forceinline__ void tf32_split(float v, float& hi, float& lo) {
    uint32 b;
    asm("cvt.rna.tf32.f32 %0, %1;" : "=r"(b) : "f"(v));
    hi = __uint_as_float(b);
    float r = v - hi;
    asm("cvt.rna.tf32.f32 %0, %1;" : "=r"(b) : "f"(r));
    lo = __uint_as_float(b);
}

__device__ __forceinline__ float tf32_rna(float v) {
    uint32 b;
    asm("cvt.rna.tf32.f32 %0, %1;" : "=r"(b) : "f"(v));
    return __uint_as_float(b);
}

__device__ __forceinline__ float sigmoidf_(float v) {
    return __fdividef(1.0f, 1.0f + __expf(-v));
}
__device__ __forceinline__ float tanhf_(float v) {
    return __fdividef(2.0f, 1.0f + __expf(-2.0f * v)) - 1.0f;
}

// D += A * B, m16n8k8 tf32 (row.col). a: 4 b32 regs, b: 2 b32 regs.
__device__ __forceinline__ void mma8(float d[4], const uint32* a, float2 b) {
    asm volatile(
        "mma.sync.aligned.m16n8k8.row.col.f32.tf32.tf32.f32 "
        "{%0,%1,%2,%3},{%4,%5,%6,%7},{%8,%9},{%0,%1,%2,%3};"
        : "+f"(d[0]), "+f"(d[1]), "+f"(d[2]), "+f"(d[3])
        : "r"(a[0]), "r"(a[1]), "r"(a[2]), "r"(a[3]),
          "r"(__float_as_uint(b.x)), "r"(__float_as_uint(b.y)));
}

// write scalar element (m,k) into A-fragment-ordered smem array
// layout: [term][mt(3)][kt(KT)][lane(32)][reg(4)] floats
__device__ __forceinline__ void frag_write(float* base, int KT, int term,
                                           int mt, int kt, int m, int k, float v) {
    int lp = ((m & 7) << 2) | (k & 3);
    int rp = ((m >> 3) & 1) | (((k >> 2) & 1) << 1);
    base[(((term * 3 + mt) * KT + kt) * 32 + lp) * 4 + rp] = v;
}

// read back element (m,k) as hi + lo
__device__ __forceinline__ float frag_read2(const float* base, int KT,
                                            int mt, int kt, int m, int k) {
    int lp = ((m & 7) << 2) | (k & 3);
    int rp = ((m >> 3) & 1) | (((k >> 2) & 1) << 1);
    return base[(((0 * 3 + mt) * KT + kt) * 32 + lp) * 4 + rp]
         + base[(((1 * 3 + mt) * KT + kt) * 32 + lp) * 4 + rp];
}

// ---------------- weight prepack into B-fragment order (hi term only) ------
__global__ void prepack(const float* __restrict__ w_ih, const float* __restrict__ w_hh,
                        const float* __restrict__ gw,  const float* __restrict__ ow)
{
    int idx = blockIdx.x * blockDim.x + threadIdx.x;   // 2688 tiles * 32 lanes
    if (idx >= 2688 * 32) return;
    int lane = idx & 31, tile = idx >> 5;
    int g = lane >> 2, tig = lane & 3;
    const float* W; float2* dst; int ld, lt;
    if      (tile < 384)  { W = w_ih; dst = g_wihP; ld = 64;  lt = tile; }
    else if (tile < 1152) { W = w_hh; dst = g_whhP; ld = 128; lt = tile - 384; }
    else if (tile < 2176) { W = gw;   dst = g_gwP;  ld = 256; lt = tile - 1152; }
    else                  { W = ow;   dst = g_owP;  ld = 256; lt = tile - 2176; }
    int KT = ld >> 3;
    int n = (lt / KT) * 8 + g;            // output row
    int k = (lt % KT) * 8 + tig;          // input col
    dst[lt * 32 + lane] = make_float2(tf32_rna(W[n * ld + k]),
                                      tf32_rna(W[n * ld + k + 4]));
}

// ---------------- Fused 2-layer GRU over T steps ----------------
__global__ __launch_bounds__(NTH, 1)
void gru_fused(const float* __restrict__ x,
               const float* __restrict__ b_ih, const float* __restrict__ b_hh,
               const float* __restrict__ gate_b, const float* __restrict__ out_b,
               float* __restrict__ out)
{
    extern __shared__ float sm[];
    float* xf  = sm;            // [2][3][8][32][4]  = 6144  (x tile, KT=8)
    float* h0f = sm + 6144;     // [2][3][16][32][4] = 12288 (layer0 h, KT=16)
    float* h1f = sm + 18432;    // 12288 (layer1 h)
    float* rhf = sm + 30720;    // 12288 (r * h1)
    const int tid = threadIdx.x;
    const int w = tid >> 5, lane = tid & 31;
    const int g = lane >> 2, tig = lane & 3;
    const int bn0 = blockIdx.x * TRR;

    // zero h0f + h1f (contiguous 24576 floats)
    for (int i = tid; i < 24576; i += NTH) h0f[i] = 0.f;

    const int c0 = 8 * w + 2 * tig;
    // layer0 biases
    float br0 = b_ih[c0]       + b_hh[c0],       br1 = b_ih[c0+1]     + b_hh[c0+1];
    float bz0 = b_ih[128 + c0] + b_hh[128 + c0], bz1 = b_ih[129 + c0] + b_hh[129 + c0];
    float bx0 = b_ih[256 + c0], bx1 = b_ih[257 + c0];
    float bh0 = b_hh[256 + c0], bh1 = b_hh[257 + c0];
    // layer1 biases
    float bgr0 = gate_b[c0],       bgr1 = gate_b[c0 + 1];
    float bgz0 = gate_b[128 + c0], bgz1 = gate_b[129 + c0];
    float bo0  = out_b[c0],        bo1  = out_b[c0 + 1];

    for (int t = 0; t < T_; ++t) {
        // ==== stage x(t): 48x64, tf32 split + A-frag store ====
        #pragma unroll
        for (int i = 0; i < 6; ++i) {
            int idx = tid + i * NTH;            // 0..3071
            int row = idx >> 6, col = idx & 63;
            int bn = bn0 + row;
            float v = (bn < BN) ? x[((size_t)bn * T_ + t) * F_ + col] : 0.f;
            float hi, lo; tf32_split(v, hi, lo);
            frag_write(xf, 8, 0, row >> 4, col >> 3, row, col, hi);
            frag_write(xf, 8, 1, row >> 4, col >> 3, row, col, lo);
        }
        __syncthreads();   // S1: xf ready; h0f/h1f from prev step ready

        // ==== layer0 GEMMs (2-term: AH*B + AL*B) ====
        float aR[3][4], aZ[3][4], aNX[3][4], aNH[3][4];
        #pragma unroll
        for (int mt = 0; mt < 3; ++mt) {
            aR[mt][0] = br0; aR[mt][1] = br1; aR[mt][2] = br0; aR[mt][3] = br1;
            aZ[mt][0] = bz0; aZ[mt][1] = bz1; aZ[mt][2] = bz0; aZ[mt][3] = bz1;
            aNX[mt][0] = bx0; aNX[mt][1] = bx1; aNX[mt][2] = bx0; aNX[mt][3] = bx1;
            aNH[mt][0] = bh0; aNH[mt][1] = bh1; aNH[mt][2] = bh0; aNH[mt][3] = bh1;
        }
        for (int kt = 0; kt < 8; ++kt) {        // x-part, K=64
            uint4 ah[3], al[3];
            #pragma unroll
            for (int mt = 0; mt < 3; ++mt) {
                ah[mt] = ((const uint4*)xf)[((0 * 3 + mt) * 8 + kt) * 32 + lane];
                al[mt] = ((const uint4*)xf)[((1 * 3 + mt) * 8 + kt) * 32 + lane];
            }
            float2 bR = g_wihP[((     w) * 8 + kt) * 32 + lane];
            float2 bZ = g_wihP[((16 + w) * 8 + kt) * 32 + lane];
            float2 bN = g_wihP[((32 + w) * 8 + kt) * 32 + lane];
            #pragma unroll
            for (int mt = 0; mt < 3; ++mt) {
                const uint32* AH = (const uint32*)&ah[mt];
                const uint32* AL = (const uint32*)&al[mt];
                mma8(aR[mt],  AH, bR); mma8(aR[mt],  AL, bR);
                mma8(aZ[mt],  AH, bZ); mma8(aZ[mt],  AL, bZ);
                mma8(aNX[mt], AH, bN); mma8(aNX[mt], AL, bN);
            }
        }
        for (int kt = 0; kt < 16; ++kt) {       // h-part, K=128 (n gate into aNH)
            uint4 ah[3], al[3];
            #pragma unroll
            for (int mt = 0; mt < 3; ++mt) {
                ah[mt] = ((const uint4*)h0f)[((0 * 3 + mt) * 16 + kt) * 32 + lane];
                al[mt] = ((const uint4*)h0f)[((1 * 3 + mt) * 16 + kt) * 32 + lane];
            }
            float2 bR = g_whhP[((     w) * 16 + kt) * 32 + lane];
            float2 bZ = g_whhP[((16 + w) * 16 + kt) * 32 + lane];
            float2 bN = g_whhP[((32 + w) * 16 + kt) * 32 + lane];
            #pragma unroll
            for (int mt = 0; mt < 3; ++mt) {
                const uint32* AH = (const uint32*)&ah[mt];
                const uint32* AL = (const uint32*)&al[mt];
                mma8(aR[mt],  AH, bR); mma8(aR[mt],  AL, bR);
                mma8(aZ[mt],  AH, bZ); mma8(aZ[mt],  AL, bZ);
                mma8(aNH[mt], AH, bN); mma8(aNH[mt], AL, bN);
            }
        }
        __syncthreads();   // S2: all reads of h0f (and xf) done

        // ==== layer0 epilogue: h0(t) -> h0f (also layer1's x input) ====
        #pragma unroll
        for (int mt = 0; mt < 3; ++mt)
            #pragma unroll
            for (int r = 0; r < 4; ++r) {
                int m   = mt * 16 + g + 8 * (r >> 1);
                int col = c0 + (r & 1);
                float hold = frag_read2(h0f, 16, mt, col >> 3, m, col);
                float rr = sigmoidf_(aR[mt][r]);
                float zz = sigmoidf_(aZ[mt][r]);
                float n  = tanhf_(aNX[mt][r] + rr * aNH[mt][r]);
                float hn = (1.f - zz) * n + zz * hold;
                float hi, lo; tf32_split(hn, hi, lo);
                frag_write(h0f, 16, 0, mt, col >> 3, m, col, hi);
                frag_write(h0f, 16, 1, mt, col >> 3, m, col, lo);
            }
        __syncthreads();   // S3: h0f(t) ready for layer1

        // ==== layer1 gates GEMM (+ candidate x-half, r-independent) ====
        float aR1[3][4], aZ1[3][4], aC[3][4];
        #pragma unroll
        for (int mt = 0; mt < 3; ++mt) {
            aR1[mt][0] = bgr0; aR1[mt][1] = bgr1; aR1[mt][2] = bgr0; aR1[mt][3] = bgr1;
            aZ1[mt][0] = bgz0; aZ1[mt][1] = bgz1; aZ1[mt][2] = bgz0; aZ1[mt][3] = bgz1;
            aC[mt][0]  = bo0;  aC[mt][1]  = bo1;  aC[mt][2]  = bo0;  aC[mt][3]  = bo1;
        }
        for (int kt = 0; kt < 16; ++kt) {       // x half: A = h0f
            uint4 ah[3], al[3];
            #pragma unroll
            for (int mt = 0; mt < 3; ++mt) {
                ah[mt] = ((const uint4*)h0f)[((0 * 3 + mt) * 16 + kt) * 32 + lane];
                al[mt] = ((const uint4*)h0f)[((1 * 3 + mt) * 16 + kt) * 32 + lane];
            }
            float2 bR = g_gwP[((     w) * 32 + kt) * 32 + lane];
            float2 bZ = g_gwP[((16 + w) * 32 + kt) * 32 + lane];
            float2 bC = g_owP[(      w  * 32 + kt) * 32 + lane];
            #pragma unroll
            for (int mt = 0; mt < 3; ++mt) {
                const uint32* AH = (const uint32*)&ah[mt];
                const uint32* AL = (const uint32*)&al[mt];
                mma8(aR1[mt], AH, bR); mma8(aR1[mt], AL, bR);
                mma8(aZ1[mt], AH, bZ); mma8(aZ1[mt], AL, bZ);
                mma8(aC[mt],  AH, bC); mma8(aC[mt],  AL, bC);
            }
        }
        for (int kt = 0; kt < 16; ++kt) {       // h half: A = h1f, gates only
            uint4 ah[3], al[3];
            #pragma unroll
            for (int mt = 0; mt < 3; ++mt) {
                ah[mt] = ((const uint4*)h1f)[((0 * 3 + mt) * 16 + kt) * 32 + lane];
                al[mt] = ((const uint4*)h1f)[((1 * 3 + mt) * 16 + kt) * 32 + lane];
            }
            float2 bR = g_gwP[((     w) * 32 + 16 + kt) * 32 + lane];
            float2 bZ = g_gwP[((16 + w) * 32 + 16 + kt) * 32 + lane];
            #pragma unroll
            for (int mt = 0; mt < 3; ++mt) {
                const uint32* AH = (const uint32*)&ah[mt];
                const uint32* AL = (const uint32*)&al[mt];
                mma8(aR1[mt], AH, bR); mma8(aR1[mt], AL, bR);
                mma8(aZ1[mt], AH, bZ); mma8(aZ1[mt], AL, bZ);
            }
        }
        __syncthreads();   // S4: all reads of h1f done

        // ==== layer1 epilogue 1: r,z ; write r*h1 frags ====
        float zz1[3][4], hold1[3][4];
        #pragma unroll
        for (int mt = 0; mt < 3; ++mt)
            #pragma unroll
            for (int r = 0; r < 4; ++r) {
                int m   = mt * 16 + g + 8 * (r >> 1);
                int col = c0 + (r & 1);
                hold1[mt][r] = frag_read2(h1f, 16, mt, col >> 3, m, col);
                float rr = sigmoidf_(aR1[mt][r]);
                zz1[mt][r] = sigmoidf_(aZ1[mt][r]);
                float rh = rr * hold1[mt][r];
                float hi, lo; tf32_split(rh, hi, lo);
                frag_write(rhf, 16, 0, mt, col >> 3, m, col, hi);
                frag_write(rhf, 16, 1, mt, col >> 3, m, col, lo);
            }
        __syncthreads();   // S5: rhf ready

        // ==== candidate r*h half ====
        for (int kt = 0; kt < 16; ++kt) {
            uint4 ah[3], al[3];
            #pragma unroll
            for (int mt = 0; mt < 3; ++mt) {
                ah[mt] = ((const uint4*)rhf)[((0 * 3 + mt) * 16 + kt) * 32 + lane];
                al[mt] = ((const uint4*)rhf)[((1 * 3 + mt) * 16 + kt) * 32 + lane];
            }
            float2 bC = g_owP[(w * 32 + 16 + kt) * 32 + lane];
            #pragma unroll
            for (int mt = 0; mt < 3; ++mt) {
                const uint32* AH = (const uint32*)&ah[mt];
                const uint32* AL = (const uint32*)&al[mt];
                mma8(aC[mt], AH, bC); mma8(aC[mt], AL, bC);
            }
        }

        // ==== layer1 epilogue 2: h1(t) -> h1f + gmem out ====
        #pragma unroll
        for (int mt = 0; mt < 3; ++mt)
            #pragma unroll
            for (int r = 0; r < 4; ++r) {
                int m   = mt * 16 + g + 8 * (r >> 1);
                int col = c0 + (r & 1);
                float cand = tanhf_(aC[mt][r]);
                float hn = zz1[mt][r] * hold1[mt][r] + (1.f - zz1[mt][r]) * cand;
                float hi, lo; tf32_split(hn, hi, lo);
                frag_write(h1f, 16, 0, mt, col >> 3, m, col, hi);
                frag_write(h1f, 16, 1, mt, col >> 3, m, col, lo);
                int bn = bn0 + m;
                if (bn < BN)
                    out[((size_t)bn * T_ + t) * H_ + col] = hn;
            }
        // next-iter S1 orders h1f/h0f writes vs. next GEMM reads;
        // xf(t+1) writes are safe: xf reads ended at S2(t).
    }
}

extern "C" void kernel_launch(void* const* d_in, const int* in_sizes, int n_in,
                              void* d_out, int out_size)
{
    const float* x      = (const float*)d_in[0];
    const float* w_ih   = (const float*)d_in[1];
    const float* w_hh   = (const float*)d_in[2];
    const float* b_ih   = (const float*)d_in[3];
    const float* b_hh   = (const float*)d_in[4];
    const float* gate_w = (const float*)d_in[5];
    const float* gate_b = (const float*)d_in[6];
    const float* out_w  = (const float*)d_in[7];
    const float* out_b  = (const float*)d_in[8];
    float* out = (float*)d_out;

    const int smem = (6144 + 3 * 12288) * 4;   // 172032 B
    cudaFuncSetAttribute(gru_fused, cudaFuncAttributeMaxDynamicSharedMemorySize, smem);

    prepack<<<168, 512>>>(w_ih, w_hh, gate_w, out_w);
    gru_fused<<<NCTA, NTH, smem>>>(x, b_ih, b_hh, gate_b, out_b, out);
}

// round 11
// speedup vs baseline: 2.9730x; 1.0856x over previous
#include <cuda_runtime.h>
#include <math.h>

#define BN   20800
#define T_   24
#define F_   64
#define H_   128
#define TRR  48
#define NCTA 434          // ceil(20800/48)
#define NTH  256          // 8 warps, 16 output cols per warp

typedef unsigned int uint32;

// ---------------- global scratch ----------------
// prepacked B-fragments (tf32 hi term only), float2 per (tile, lane)  [m16n8k8]
__device__ float2 g_wihP[384  * 32];   // w_ih  [384x64]  : 48 nt x 8 kt
__device__ float2 g_whhP[768  * 32];   // w_hh  [384x128] : 48 nt x 16 kt
__device__ float2 g_gwP [1024 * 32];   // gate_w[256x256] : 32 nt x 32 kt
__device__ float2 g_owP [512  * 32];   // out_w [128x256] : 16 nt x 32 kt

// ---------------- helpers ----------------
__device__ __forceinline__ void tf32_split(float v, float& hi, float& lo) {
    uint32 b;
    asm("cvt.rna.tf32.f32 %0, %1;" : "=r"(b) : "f"(v));
    hi = __uint_as_float(b);
    float r = v - hi;
    asm("cvt.rna.tf32.f32 %0, %1;" : "=r"(b) : "f"(r));
    lo = __uint_as_float(b);
}

__device__ __forceinline__ float tf32_rna(float v) {
    uint32 b;
    asm("cvt.rna.tf32.f32 %0, %1;" : "=r"(b) : "f"(v));
    return __uint_as_float(b);
}

__device__ __forceinline__ float sigmoidf_(float v) {
    return __fdividef(1.0f, 1.0f + __expf(-v));
}
__device__ __forceinline__ float tanhf_(float v) {
    return __fdividef(2.0f, 1.0f + __expf(-2.0f * v)) - 1.0f;
}

// D += A * B, m16n8k8 tf32 (row.col). a: 4 b32 regs, b: 2 b32 regs.
__device__ __forceinline__ void mma8(float d[4], const uint32* a, float2 b) {
    asm volatile(
        "mma.sync.aligned.m16n8k8.row.col.f32.tf32.tf32.f32 "
        "{%0,%1,%2,%3},{%4,%5,%6,%7},{%8,%9},{%0,%1,%2,%3};"
        : "+f"(d[0]), "+f"(d[1]), "+f"(d[2]), "+f"(d[3])
        : "r"(a[0]), "r"(a[1]), "r"(a[2]), "r"(a[3]),
          "r"(__float_as_uint(b.x)), "r"(__float_as_uint(b.y)));
}

// write scalar element (m,k) into A-fragment-ordered smem array
// layout: [term][mt(3)][kt(KT)][lane(32)][reg(4)] floats
__device__ __forceinline__ void frag_write(float* base, int KT, int term,
                                           int mt, int kt, int m, int k, float v) {
    int lp = ((m & 7) << 2) | (k & 3);
    int rp = ((m >> 3) & 1) | (((k >> 2) & 1) << 1);
    base[(((term * 3 + mt) * KT + kt) * 32 + lp) * 4 + rp] = v;
}

// read back element (m,k) as hi + lo
__device__ __forceinline__ float frag_read2(const float* base, int KT,
                                            int mt, int kt, int m, int k) {
    int lp = ((m & 7) << 2) | (k & 3);
    int rp = ((m >> 3) & 1) | (((k >> 2) & 1) << 1);
    return base[(((0 * 3 + mt) * KT + kt) * 32 + lp) * 4 + rp]
         + base[(((1 * 3 + mt) * KT + kt) * 32 + lp) * 4 + rp];
}

// ---------------- weight prepack into B-fragment order (hi term only) ------
__global__ void prepack(const float* __restrict__ w_ih, const float* __restrict__ w_hh,
                        const float* __restrict__ gw,  const float* __restrict__ ow)
{
    int idx = blockIdx.x * blockDim.x + threadIdx.x;   // 2688 tiles * 32 lanes
    if (idx >= 2688 * 32) return;
    int lane = idx & 31, tile = idx >> 5;
    int g = lane >> 2, tig = lane & 3;
    const float* W; float2* dst; int ld, lt;
    if      (tile < 384)  { W = w_ih; dst = g_wihP; ld = 64;  lt = tile; }
    else if (tile < 1152) { W = w_hh; dst = g_whhP; ld = 128; lt = tile - 384; }
    else if (tile < 2176) { W = gw;   dst = g_gwP;  ld = 256; lt = tile - 1152; }
    else                  { W = ow;   dst = g_owP;  ld = 256; lt = tile - 2176; }
    int KT = ld >> 3;
    int n = (lt / KT) * 8 + g;            // output row
    int k = (lt % KT) * 8 + tig;          // input col
    dst[lt * 32 + lane] = make_float2(tf32_rna(W[n * ld + k]),
                                      tf32_rna(W[n * ld + k + 4]));
}

// ---------------- Fused 2-layer GRU over T steps ----------------
// 8 warps; warp w owns output columns [16w, 16w+16) = n8 blocks {2w, 2w+1}.
__global__ __launch_bounds__(NTH, 1)
void gru_fused(const float* __restrict__ x,
               const float* __restrict__ b_ih, const float* __restrict__ b_hh,
               const float* __restrict__ gate_b, const float* __restrict__ out_b,
               float* __restrict__ out)
{
    extern __shared__ float sm[];
    float* xf  = sm;            // [2][3][8][32][4]  = 6144  (x tile, KT=8)
    float* h0f = sm + 6144;     // [2][3][16][32][4] = 12288 (layer0 h, KT=16)
    float* h1f = sm + 18432;    // 12288 (layer1 h)
    float* rhf = sm + 30720;    // 12288 (r * h1)
    const int tid = threadIdx.x;
    const int w = tid >> 5, lane = tid & 31;
    const int g = lane >> 2, tig = lane & 3;
    const int bn0 = blockIdx.x * TRR;

    // zero h0f + h1f (contiguous 24576 floats)
    for (int i = tid; i < 24576; i += NTH) h0f[i] = 0.f;

    // biases per n-block nb (col base = 16w + 8nb + 2tig)
    float br0[2], br1[2], bz0[2], bz1[2], bx0[2], bx1[2], bh0[2], bh1[2];
    float bgr0[2], bgr1[2], bgz0[2], bgz1[2], bo0[2], bo1[2];
    #pragma unroll
    for (int nb = 0; nb < 2; ++nb) {
        int c0 = 16 * w + 8 * nb + 2 * tig;
        br0[nb] = b_ih[c0]       + b_hh[c0];       br1[nb] = b_ih[c0+1]     + b_hh[c0+1];
        bz0[nb] = b_ih[128 + c0] + b_hh[128 + c0]; bz1[nb] = b_ih[129 + c0] + b_hh[129 + c0];
        bx0[nb] = b_ih[256 + c0];  bx1[nb] = b_ih[257 + c0];
        bh0[nb] = b_hh[256 + c0];  bh1[nb] = b_hh[257 + c0];
        bgr0[nb] = gate_b[c0];        bgr1[nb] = gate_b[c0 + 1];
        bgz0[nb] = gate_b[128 + c0];  bgz1[nb] = gate_b[129 + c0];
        bo0[nb]  = out_b[c0];         bo1[nb]  = out_b[c0 + 1];
    }

    for (int t = 0; t < T_; ++t) {
        // ==== stage x(t): 48x64, tf32 split + A-frag store ====
        #pragma unroll
        for (int i = 0; i < 12; ++i) {
            int idx = tid + i * NTH;            // 0..3071
            int row = idx >> 6, col = idx & 63;
            int bn = bn0 + row;
            float v = (bn < BN) ? x[((size_t)bn * T_ + t) * F_ + col] : 0.f;
            float hi, lo; tf32_split(v, hi, lo);
            frag_write(xf, 8, 0, row >> 4, col >> 3, row, col, hi);
            frag_write(xf, 8, 1, row >> 4, col >> 3, row, col, lo);
        }
        __syncthreads();   // S1: xf ready; h0f/h1f from prev step ready

        // ==== layer0 GEMMs (2-term: AH*B + AL*B), 2 n-blocks per warp ====
        float aR[3][2][4], aZ[3][2][4], aNX[3][2][4], aNH[3][2][4];
        #pragma unroll
        for (int mt = 0; mt < 3; ++mt)
            #pragma unroll
            for (int nb = 0; nb < 2; ++nb) {
                aR[mt][nb][0] = br0[nb]; aR[mt][nb][1] = br1[nb];
                aR[mt][nb][2] = br0[nb]; aR[mt][nb][3] = br1[nb];
                aZ[mt][nb][0] = bz0[nb]; aZ[mt][nb][1] = bz1[nb];
                aZ[mt][nb][2] = bz0[nb]; aZ[mt][nb][3] = bz1[nb];
                aNX[mt][nb][0] = bx0[nb]; aNX[mt][nb][1] = bx1[nb];
                aNX[mt][nb][2] = bx0[nb]; aNX[mt][nb][3] = bx1[nb];
                aNH[mt][nb][0] = bh0[nb]; aNH[mt][nb][1] = bh1[nb];
                aNH[mt][nb][2] = bh0[nb]; aNH[mt][nb][3] = bh1[nb];
            }
        for (int kt = 0; kt < 8; ++kt) {        // x-part, K=64
            uint4 ah[3], al[3];
            #pragma unroll
            for (int mt = 0; mt < 3; ++mt) {
                ah[mt] = ((const uint4*)xf)[((0 * 3 + mt) * 8 + kt) * 32 + lane];
                al[mt] = ((const uint4*)xf)[((1 * 3 + mt) * 8 + kt) * 32 + lane];
            }
            float2 bR[2], bZ[2], bN[2];
            #pragma unroll
            for (int nb = 0; nb < 2; ++nb) {
                int nt = 2 * w + nb;
                bR[nb] = g_wihP[((     nt) * 8 + kt) * 32 + lane];
                bZ[nb] = g_wihP[((16 + nt) * 8 + kt) * 32 + lane];
                bN[nb] = g_wihP[((32 + nt) * 8 + kt) * 32 + lane];
            }
            #pragma unroll
            for (int mt = 0; mt < 3; ++mt) {
                const uint32* AH = (const uint32*)&ah[mt];
                const uint32* AL = (const uint32*)&al[mt];
                #pragma unroll
                for (int nb = 0; nb < 2; ++nb) {
                    mma8(aR[mt][nb],  AH, bR[nb]); mma8(aR[mt][nb],  AL, bR[nb]);
                    mma8(aZ[mt][nb],  AH, bZ[nb]); mma8(aZ[mt][nb],  AL, bZ[nb]);
                    mma8(aNX[mt][nb], AH, bN[nb]); mma8(aNX[mt][nb], AL, bN[nb]);
                }
            }
        }
        for (int kt = 0; kt < 16; ++kt) {       // h-part, K=128 (n gate into aNH)
            uint4 ah[3], al[3];
            #pragma unroll
            for (int mt = 0; mt < 3; ++mt) {
                ah[mt] = ((const uint4*)h0f)[((0 * 3 + mt) * 16 + kt) * 32 + lane];
                al[mt] = ((const uint4*)h0f)[((1 * 3 + mt) * 16 + kt) * 32 + lane];
            }
            float2 bR[2], bZ[2], bN[2];
            #pragma unroll
            for (int nb = 0; nb < 2; ++nb) {
                int nt = 2 * w + nb;
                bR[nb] = g_whhP[((     nt) * 16 + kt) * 32 + lane];
                bZ[nb] = g_whhP[((16 + nt) * 16 + kt) * 32 + lane];
                bN[nb] = g_whhP[((32 + nt) * 16 + kt) * 32 + lane];
            }
            #pragma unroll
            for (int mt = 0; mt < 3; ++mt) {
                const uint32* AH = (const uint32*)&ah[mt];
                const uint32* AL = (const uint32*)&al[mt];
                #pragma unroll
                for (int nb = 0; nb < 2; ++nb) {
                    mma8(aR[mt][nb],  AH, bR[nb]); mma8(aR[mt][nb],  AL, bR[nb]);
                    mma8(aZ[mt][nb],  AH, bZ[nb]); mma8(aZ[mt][nb],  AL, bZ[nb]);
                    mma8(aNH[mt][nb], AH, bN[nb]); mma8(aNH[mt][nb], AL, bN[nb]);
                }
            }
        }
        __syncthreads();   // S2: all reads of h0f (and xf) done

        // ==== layer0 epilogue: h0(t) -> h0f ====
        #pragma unroll
        for (int mt = 0; mt < 3; ++mt)
            #pragma unroll
            for (int nb = 0; nb < 2; ++nb)
                #pragma unroll
                for (int r = 0; r < 4; ++r) {
                    int m   = mt * 16 + g + 8 * (r >> 1);
                    int col = 16 * w + 8 * nb + 2 * tig + (r & 1);
                    float hold = frag_read2(h0f, 16, mt, col >> 3, m, col);
                    float rr = sigmoidf_(aR[mt][nb][r]);
                    float zz = sigmoidf_(aZ[mt][nb][r]);
                    float n  = tanhf_(aNX[mt][nb][r] + rr * aNH[mt][nb][r]);
                    float hn = (1.f - zz) * n + zz * hold;
                    float hi, lo; tf32_split(hn, hi, lo);
                    frag_write(h0f, 16, 0, mt, col >> 3, m, col, hi);
                    frag_write(h0f, 16, 1, mt, col >> 3, m, col, lo);
                }
        __syncthreads();   // S3: h0f(t) ready for layer1

        // ==== layer1 gates GEMM (+ candidate x-half) ====
        float aR1[3][2][4], aZ1[3][2][4], aC[3][2][4];
        #pragma unroll
        for (int mt = 0; mt < 3; ++mt)
            #pragma unroll
            for (int nb = 0; nb < 2; ++nb) {
                aR1[mt][nb][0] = bgr0[nb]; aR1[mt][nb][1] = bgr1[nb];
                aR1[mt][nb][2] = bgr0[nb]; aR1[mt][nb][3] = bgr1[nb];
                aZ1[mt][nb][0] = bgz0[nb]; aZ1[mt][nb][1] = bgz1[nb];
                aZ1[mt][nb][2] = bgz0[nb]; aZ1[mt][nb][3] = bgz1[nb];
                aC[mt][nb][0]  = bo0[nb];  aC[mt][nb][1]  = bo1[nb];
                aC[mt][nb][2]  = bo0[nb];  aC[mt][nb][3]  = bo1[nb];
            }
        for (int kt = 0; kt < 16; ++kt) {       // x half: A = h0f
            uint4 ah[3], al[3];
            #pragma unroll
            for (int mt = 0; mt < 3; ++mt) {
                ah[mt] = ((const uint4*)h0f)[((0 * 3 + mt) * 16 + kt) * 32 + lane];
                al[mt] = ((const uint4*)h0f)[((1 * 3 + mt) * 16 + kt) * 32 + lane];
            }
            float2 bR[2], bZ[2], bC[2];
            #pragma unroll
            for (int nb = 0; nb < 2; ++nb) {
                int nt = 2 * w + nb;
                bR[nb] = g_gwP[((     nt) * 32 + kt) * 32 + lane];
                bZ[nb] = g_gwP[((16 + nt) * 32 + kt) * 32 + lane];
                bC[nb] = g_owP[(      nt  * 32 + kt) * 32 + lane];
            }
            #pragma unroll
            for (int mt = 0; mt < 3; ++mt) {
                const uint32* AH = (const uint32*)&ah[mt];
                const uint32* AL = (const uint32*)&al[mt];
                #pragma unroll
                for (int nb = 0; nb < 2; ++nb) {
                    mma8(aR1[mt][nb], AH, bR[nb]); mma8(aR1[mt][nb], AL, bR[nb]);
                    mma8(aZ1[mt][nb], AH, bZ[nb]); mma8(aZ1[mt][nb], AL, bZ[nb]);
                    mma8(aC[mt][nb],  AH, bC[nb]); mma8(aC[mt][nb],  AL, bC[nb]);
                }
            }
        }
        for (int kt = 0; kt < 16; ++kt) {       // h half: A = h1f, gates only
            uint4 ah[3], al[3];
            #pragma unroll
            for (int mt = 0; mt < 3; ++mt) {
                ah[mt] = ((const uint4*)h1f)[((0 * 3 + mt) * 16 + kt) * 32 + lane];
                al[mt] = ((const uint4*)h1f)[((1 * 3 + mt) * 16 + kt) * 32 + lane];
            }
            float2 bR[2], bZ[2];
            #pragma unroll
            for (int nb = 0; nb < 2; ++nb) {
                int nt = 2 * w + nb;
                bR[nb] = g_gwP[((     nt) * 32 + 16 + kt) * 32 + lane];
                bZ[nb] = g_gwP[((16 + nt) * 32 + 16 + kt) * 32 + lane];
            }
            #pragma unroll
            for (int mt = 0; mt < 3; ++mt) {
                const uint32* AH = (const uint32*)&ah[mt];
                const uint32* AL = (const uint32*)&al[mt];
                #pragma unroll
                for (int nb = 0; nb < 2; ++nb) {
                    mma8(aR1[mt][nb], AH, bR[nb]); mma8(aR1[mt][nb], AL, bR[nb]);
                    mma8(aZ1[mt][nb], AH, bZ[nb]); mma8(aZ1[mt][nb], AL, bZ[nb]);
                }
            }
        }
        __syncthreads();   // S4: all reads of h1f done

        // ==== layer1 epilogue 1: r,z ; write r*h1 frags ====
        float zz1[3][2][4], hold1[3][2][4];
        #pragma unroll
        for (int mt = 0; mt < 3; ++mt)
            #pragma unroll
            for (int nb = 0; nb < 2; ++nb)
                #pragma unroll
                for (int r = 0; r < 4; ++r) {
                    int m   = mt * 16 + g + 8 * (r >> 1);
                    int col = 16 * w + 8 * nb + 2 * tig + (r & 1);
                    hold1[mt][nb][r] = frag_read2(h1f, 16, mt, col >> 3, m, col);
                    float rr = sigmoidf_(aR1[mt][nb][r]);
                    zz1[mt][nb][r] = sigmoidf_(aZ1[mt][nb][r]);
                    float rh = rr * hold1[mt][nb][r];
                    float hi, lo; tf32_split(rh, hi, lo);
                    frag_write(rhf, 16, 0, mt, col >> 3, m, col, hi);
                    frag_write(rhf, 16, 1, mt, col >> 3, m, col, lo);
                }
        __syncthreads();   // S5: rhf ready

        // ==== candidate r*h half ====
        for (int kt = 0; kt < 16; ++kt) {
            uint4 ah[3], al[3];
            #pragma unroll
            for (int mt = 0; mt < 3; ++mt) {
                ah[mt] = ((const uint4*)rhf)[((0 * 3 + mt) * 16 + kt) * 32 + lane];
                al[mt] = ((const uint4*)rhf)[((1 * 3 + mt) * 16 + kt) * 32 + lane];
            }
            float2 bC[2];
            #pragma unroll
            for (int nb = 0; nb < 2; ++nb)
                bC[nb] = g_owP[((2 * w + nb) * 32 + 16 + kt) * 32 + lane];
            #pragma unroll
            for (int mt = 0; mt < 3; ++mt) {
                const uint32* AH = (const uint32*)&ah[mt];
                const uint32* AL = (const uint32*)&al[mt];
                #pragma unroll
                for (int nb = 0; nb < 2; ++nb) {
                    mma8(aC[mt][nb], AH, bC[nb]); mma8(aC[mt][nb], AL, bC[nb]);
                }
            }
        }

        // ==== layer1 epilogue 2: h1(t) -> h1f + gmem out (STG.64 pairs) ====
        #pragma unroll
        for (int mt = 0; mt < 3; ++mt)
            #pragma unroll
            for (int nb = 0; nb < 2; ++nb)
                #pragma unroll
                for (int rh = 0; rh < 2; ++rh) {
                    int m  = mt * 16 + g + 8 * rh;
                    int c0 = 16 * w + 8 * nb + 2 * tig;
                    float hn2[2];
                    #pragma unroll
                    for (int c = 0; c < 2; ++c) {
                        int r = rh * 2 + c;
                        float cand = tanhf_(aC[mt][nb][r]);
                        float hn = zz1[mt][nb][r] * hold1[mt][nb][r]
                                 + (1.f - zz1[mt][nb][r]) * cand;
                        float hi, lo; tf32_split(hn, hi, lo);
                        frag_write(h1f, 16, 0, mt, c0 >> 3, m, c0 + c, hi);
                        frag_write(h1f, 16, 1, mt, c0 >> 3, m, c0 + c, lo);
                        hn2[c] = hn;
                    }
                    int bn = bn0 + m;
                    if (bn < BN)
                        *reinterpret_cast<float2*>(out + ((size_t)bn * T_ + t) * H_ + c0)
                            = make_float2(hn2[0], hn2[1]);
                }
        // next-iter S1 orders h1f/h0f writes vs. next GEMM reads;
        // xf(t+1) writes are safe: xf reads ended at S2(t).
    }
}

extern "C" void kernel_launch(void* const* d_in, const int* in_sizes, int n_in,
                              void* d_out, int out_size)
{
    const float* x      = (const float*)d_in[0];
    const float* w_ih   = (const float*)d_in[1];
    const float* w_hh   = (const float*)d_in[2];
    const float* b_ih   = (const float*)d_in[3];
    const float* b_hh   = (const float*)d_in[4];
    const float* gate_b = (const float*)d_in[5];
    const float* gate_w = (const float*)d_in[5];
    const float* gate_b_ = (const float*)d_in[6];
    const float* out_w  = (const float*)d_in[7];
    const float* out_b  = (const float*)d_in[8];
    float* out = (float*)d_out;

    const int smem = (6144 + 3 * 12288) * 4;   // 172032 B
    cudaFuncSetAttribute(gru_fused, cudaFuncAttributeMaxDynamicSharedMemorySize, smem);

    prepack<<<168, 512>>>(w_ih, w_hh, gate_w, out_w);
    gru_fused<<<NCTA, NTH, smem>>>(x, b_ih, b_hh, gate_b_, out_b, out);
}

// round 12
// speedup vs baseline: 3.0306x; 1.0194x over previous
#include <cuda_runtime.h>
#include <math.h>

#define BN   20800
#define T_   24
#define F_   64
#define H_   128
#define TRR  48
#define NCTA 434          // ceil(20800/48)
#define NTH  256          // 8 warps, 16 output cols per warp

typedef unsigned int uint32;

// ---------------- global scratch ----------------
// prepacked B-fragments (tf32 hi term only), float2 per (tile, lane)  [m16n8k8]
__device__ float2 g_wihP[384  * 32];   // w_ih  [384x64]  : 48 nt x 8 kt
__device__ float2 g_whhP[768  * 32];   // w_hh  [384x128] : 48 nt x 16 kt
__device__ float2 g_gwP [1024 * 32];   // gate_w[256x256] : 32 nt x 32 kt
__device__ float2 g_owP [512  * 32];   // out_w [128x256] : 16 nt x 32 kt

// ---------------- helpers ----------------
__device__ __forceinline__ void tf32_split(float v, float& hi, float& lo) {
    uint32 b;
    asm("cvt.rna.tf32.f32 %0, %1;" : "=r"(b) : "f"(v));
    hi = __uint_as_float(b);
    float r = v - hi;
    asm("cvt.rna.tf32.f32 %0, %1;" : "=r"(b) : "f"(r));
    lo = __uint_as_float(b);
}

__device__ __forceinline__ float tf32_rna(float v) {
    uint32 b;
    asm("cvt.rna.tf32.f32 %0, %1;" : "=r"(b) : "f"(v));
    return __uint_as_float(b);
}

__device__ __forceinline__ float sigmoidf_(float v) {
    return __fdividef(1.0f, 1.0f + __expf(-v));
}
__device__ __forceinline__ float tanhf_(float v) {
    return __fdividef(2.0f, 1.0f + __expf(-2.0f * v)) - 1.0f;
}

// D += A * B, m16n8k8 tf32 (row.col). a: 4 b32 regs, b: 2 b32 regs.
__device__ __forceinline__ void mma8(float d[4], const uint32* a, float2 b) {
    asm volatile(
        "mma.sync.aligned.m16n8k8.row.col.f32.tf32.tf32.f32 "
        "{%0,%1,%2,%3},{%4,%5,%6,%7},{%8,%9},{%0,%1,%2,%3};"
        : "+f"(d[0]), "+f"(d[1]), "+f"(d[2]), "+f"(d[3])
        : "r"(a[0]), "r"(a[1]), "r"(a[2]), "r"(a[3]),
          "r"(__float_as_uint(b.x)), "r"(__float_as_uint(b.y)));
}

// write scalar element (m,k) into A-fragment-ordered smem array
// layout: [term][mt(3)][kt(KT)][lane(32)][reg(4)] floats
__device__ __forceinline__ void frag_write(float* base, int KT, int term,
                                           int mt, int kt, int m, int k, float v) {
    int lp = ((m & 7) << 2) | (k & 3);
    int rp = ((m >> 3) & 1) | (((k >> 2) & 1) << 1);
    base[(((term * 3 + mt) * KT + kt) * 32 + lp) * 4 + rp] = v;
}

// read back element (m,k) as hi + lo
__device__ __forceinline__ float frag_read2(const float* base, int KT,
                                            int mt, int kt, int m, int k) {
    int lp = ((m & 7) << 2) | (k & 3);
    int rp = ((m >> 3) & 1) | (((k >> 2) & 1) << 1);
    return base[(((0 * 3 + mt) * KT + kt) * 32 + lp) * 4 + rp]
         + base[(((1 * 3 + mt) * KT + kt) * 32 + lp) * 4 + rp];
}

// ---------------- weight prepack into B-fragment order (hi term only) ------
__global__ void prepack(const float* __restrict__ w_ih, const float* __restrict__ w_hh,
                        const float* __restrict__ gw,  const float* __restrict__ ow)
{
    int idx = blockIdx.x * blockDim.x + threadIdx.x;   // 2688 tiles * 32 lanes
    if (idx >= 2688 * 32) return;
    int lane = idx & 31, tile = idx >> 5;
    int g = lane >> 2, tig = lane & 3;
    const float* W; float2* dst; int ld, lt;
    if      (tile < 384)  { W = w_ih; dst = g_wihP; ld = 64;  lt = tile; }
    else if (tile < 1152) { W = w_hh; dst = g_whhP; ld = 128; lt = tile - 384; }
    else if (tile < 2176) { W = gw;   dst = g_gwP;  ld = 256; lt = tile - 1152; }
    else                  { W = ow;   dst = g_owP;  ld = 256; lt = tile - 2176; }
    int KT = ld >> 3;
    int n = (lt / KT) * 8 + g;            // output row
    int k = (lt % KT) * 8 + tig;          // input col
    dst[lt * 32 + lane] = make_float2(tf32_rna(W[n * ld + k]),
                                      tf32_rna(W[n * ld + k + 4]));
}

// ---------------- Fused 2-layer GRU over T steps ----------------
// 8 warps; warp w owns output columns [16w, 16w+16) = n8 blocks {2w, 2w+1}.
// 3 barriers per timestep; x(t+1) staging overlapped with layer1 gates GEMM.
__global__ __launch_bounds__(NTH, 1)
void gru_fused(const float* __restrict__ x,
               const float* __restrict__ b_ih, const float* __restrict__ b_hh,
               const float* __restrict__ gate_b, const float* __restrict__ out_b,
               float* __restrict__ out)
{
    extern __shared__ float sm[];
    float* xf  = sm;            // [2][3][8][32][4]  = 6144  (x tile, KT=8)
    float* h0f = sm + 6144;     // [2][3][16][32][4] = 12288 (layer0 h, KT=16)
    float* h1f = sm + 18432;    // 12288 (layer1 h)
    float* rhf = sm + 30720;    // 12288 (r * h1)
    const int tid = threadIdx.x;
    const int w = tid >> 5, lane = tid & 31;
    const int g = lane >> 2, tig = lane & 3;
    const int bn0 = blockIdx.x * TRR;

    // zero h0f + h1f (contiguous 24576 floats)
    for (int i = tid; i < 24576; i += NTH) h0f[i] = 0.f;

    // biases per n-block nb (col base = 16w + 8nb + 2tig)
    float br0[2], br1[2], bz0[2], bz1[2], bx0[2], bx1[2], bh0[2], bh1[2];
    float bgr0[2], bgr1[2], bgz0[2], bgz1[2], bo0[2], bo1[2];
    #pragma unroll
    for (int nb = 0; nb < 2; ++nb) {
        int c0 = 16 * w + 8 * nb + 2 * tig;
        br0[nb] = b_ih[c0]       + b_hh[c0];       br1[nb] = b_ih[c0+1]     + b_hh[c0+1];
        bz0[nb] = b_ih[128 + c0] + b_hh[128 + c0]; bz1[nb] = b_ih[129 + c0] + b_hh[129 + c0];
        bx0[nb] = b_ih[256 + c0];  bx1[nb] = b_ih[257 + c0];
        bh0[nb] = b_hh[256 + c0];  bh1[nb] = b_hh[257 + c0];
        bgr0[nb] = gate_b[c0];        bgr1[nb] = gate_b[c0 + 1];
        bgz0[nb] = gate_b[128 + c0];  bgz1[nb] = gate_b[129 + c0];
        bo0[nb]  = out_b[c0];         bo1[nb]  = out_b[c0 + 1];
    }

    // stage x(0)
    #pragma unroll
    for (int i = 0; i < 12; ++i) {
        int idx = tid + i * NTH;            // 0..3071
        int row = idx >> 6, col = idx & 63;
        int bn = bn0 + row;
        float v = (bn < BN) ? x[(size_t)bn * T_ * F_ + col] : 0.f;
        float hi, lo; tf32_split(v, hi, lo);
        frag_write(xf, 8, 0, row >> 4, col >> 3, row, col, hi);
        frag_write(xf, 8, 1, row >> 4, col >> 3, row, col, lo);
    }
    __syncthreads();   // init + x(0) visible

    for (int t = 0; t < T_; ++t) {
        // ==== layer0 GEMMs (2-term: AH*B + AL*B), 2 n-blocks per warp ====
        float aR[3][2][4], aZ[3][2][4], aNX[3][2][4], aNH[3][2][4];
        #pragma unroll
        for (int mt = 0; mt < 3; ++mt)
            #pragma unroll
            for (int nb = 0; nb < 2; ++nb) {
                aR[mt][nb][0] = br0[nb]; aR[mt][nb][1] = br1[nb];
                aR[mt][nb][2] = br0[nb]; aR[mt][nb][3] = br1[nb];
                aZ[mt][nb][0] = bz0[nb]; aZ[mt][nb][1] = bz1[nb];
                aZ[mt][nb][2] = bz0[nb]; aZ[mt][nb][3] = bz1[nb];
                aNX[mt][nb][0] = bx0[nb]; aNX[mt][nb][1] = bx1[nb];
                aNX[mt][nb][2] = bx0[nb]; aNX[mt][nb][3] = bx1[nb];
                aNH[mt][nb][0] = bh0[nb]; aNH[mt][nb][1] = bh1[nb];
                aNH[mt][nb][2] = bh0[nb]; aNH[mt][nb][3] = bh1[nb];
            }
        for (int kt = 0; kt < 8; ++kt) {        // x-part, K=64
            uint4 ah[3], al[3];
            #pragma unroll
            for (int mt = 0; mt < 3; ++mt) {
                ah[mt] = ((const uint4*)xf)[((0 * 3 + mt) * 8 + kt) * 32 + lane];
                al[mt] = ((const uint4*)xf)[((1 * 3 + mt) * 8 + kt) * 32 + lane];
            }
            float2 bR[2], bZ[2], bN[2];
            #pragma unroll
            for (int nb = 0; nb < 2; ++nb) {
                int nt = 2 * w + nb;
                bR[nb] = g_wihP[((     nt) * 8 + kt) * 32 + lane];
                bZ[nb] = g_wihP[((16 + nt) * 8 + kt) * 32 + lane];
                bN[nb] = g_wihP[((32 + nt) * 8 + kt) * 32 + lane];
            }
            #pragma unroll
            for (int mt = 0; mt < 3; ++mt) {
                const uint32* AH = (const uint32*)&ah[mt];
                const uint32* AL = (const uint32*)&al[mt];
                #pragma unroll
                for (int nb = 0; nb < 2; ++nb) {
                    mma8(aR[mt][nb],  AH, bR[nb]); mma8(aR[mt][nb],  AL, bR[nb]);
                    mma8(aZ[mt][nb],  AH, bZ[nb]); mma8(aZ[mt][nb],  AL, bZ[nb]);
                    mma8(aNX[mt][nb], AH, bN[nb]); mma8(aNX[mt][nb], AL, bN[nb]);
                }
            }
        }
        for (int kt = 0; kt < 16; ++kt) {       // h-part, K=128 (n gate into aNH)
            uint4 ah[3], al[3];
            #pragma unroll
            for (int mt = 0; mt < 3; ++mt) {
                ah[mt] = ((const uint4*)h0f)[((0 * 3 + mt) * 16 + kt) * 32 + lane];
                al[mt] = ((const uint4*)h0f)[((1 * 3 + mt) * 16 + kt) * 32 + lane];
            }
            float2 bR[2], bZ[2], bN[2];
            #pragma unroll
            for (int nb = 0; nb < 2; ++nb) {
                int nt = 2 * w + nb;
                bR[nb] = g_whhP[((     nt) * 16 + kt) * 32 + lane];
                bZ[nb] = g_whhP[((16 + nt) * 16 + kt) * 32 + lane];
                bN[nb] = g_whhP[((32 + nt) * 16 + kt) * 32 + lane];
            }
            #pragma unroll
            for (int mt = 0; mt < 3; ++mt) {
                const uint32* AH = (const uint32*)&ah[mt];
                const uint32* AL = (const uint32*)&al[mt];
                #pragma unroll
                for (int nb = 0; nb < 2; ++nb) {
                    mma8(aR[mt][nb],  AH, bR[nb]); mma8(aR[mt][nb],  AL, bR[nb]);
                    mma8(aZ[mt][nb],  AH, bZ[nb]); mma8(aZ[mt][nb],  AL, bZ[nb]);
                    mma8(aNH[mt][nb], AH, bN[nb]); mma8(aNH[mt][nb], AL, bN[nb]);
                }
            }
        }
        __syncthreads();   // S2: all reads of h0f/xf done

        // ==== layer0 epilogue: h0(t) -> h0f ====
        #pragma unroll
        for (int mt = 0; mt < 3; ++mt)
            #pragma unroll
            for (int nb = 0; nb < 2; ++nb)
                #pragma unroll
                for (int r = 0; r < 4; ++r) {
                    int m   = mt * 16 + g + 8 * (r >> 1);
                    int col = 16 * w + 8 * nb + 2 * tig + (r & 1);
                    float hold = frag_read2(h0f, 16, mt, col >> 3, m, col);
                    float rr = sigmoidf_(aR[mt][nb][r]);
                    float zz = sigmoidf_(aZ[mt][nb][r]);
                    float n  = tanhf_(aNX[mt][nb][r] + rr * aNH[mt][nb][r]);
                    float hn = (1.f - zz) * n + zz * hold;
                    float hi, lo; tf32_split(hn, hi, lo);
                    frag_write(h0f, 16, 0, mt, col >> 3, m, col, hi);
                    frag_write(h0f, 16, 1, mt, col >> 3, m, col, lo);
                }
        __syncthreads();   // S3: h0f(t) ready for layer1

        // ==== stage x(t+1) into xf (overlaps with gates GEMM below) ====
        // xf's last reader was layer0 GEMM (pre-S2); next reader is layer0
        // GEMM at t+1 (post-S5). Writes here are barrier-ordered both ways.
        if (t + 1 < T_) {
            #pragma unroll
            for (int i = 0; i < 12; ++i) {
                int idx = tid + i * NTH;        // 0..3071
                int row = idx >> 6, col = idx & 63;
                int bn = bn0 + row;
                float v = (bn < BN) ? x[((size_t)bn * T_ + t + 1) * F_ + col] : 0.f;
                float hi, lo; tf32_split(v, hi, lo);
                frag_write(xf, 8, 0, row >> 4, col >> 3, row, col, hi);
                frag_write(xf, 8, 1, row >> 4, col >> 3, row, col, lo);
            }
        }

        // ==== layer1 gates GEMM (+ candidate x-half) ====
        float aR1[3][2][4], aZ1[3][2][4], aC[3][2][4];
        #pragma unroll
        for (int mt = 0; mt < 3; ++mt)
            #pragma unroll
            for (int nb = 0; nb < 2; ++nb) {
                aR1[mt][nb][0] = bgr0[nb]; aR1[mt][nb][1] = bgr1[nb];
                aR1[mt][nb][2] = bgr0[nb]; aR1[mt][nb][3] = bgr1[nb];
                aZ1[mt][nb][0] = bgz0[nb]; aZ1[mt][nb][1] = bgz1[nb];
                aZ1[mt][nb][2] = bgz0[nb]; aZ1[mt][nb][3] = bgz1[nb];
                aC[mt][nb][0]  = bo0[nb];  aC[mt][nb][1]  = bo1[nb];
                aC[mt][nb][2]  = bo0[nb];  aC[mt][nb][3]  = bo1[nb];
            }
        for (int kt = 0; kt < 16; ++kt) {       // x half: A = h0f
            uint4 ah[3], al[3];
            #pragma unroll
            for (int mt = 0; mt < 3; ++mt) {
                ah[mt] = ((const uint4*)h0f)[((0 * 3 + mt) * 16 + kt) * 32 + lane];
                al[mt] = ((const uint4*)h0f)[((1 * 3 + mt) * 16 + kt) * 32 + lane];
            }
            float2 bR[2], bZ[2], bC[2];
            #pragma unroll
            for (int nb = 0; nb < 2; ++nb) {
                int nt = 2 * w + nb;
                bR[nb] = g_gwP[((     nt) * 32 + kt) * 32 + lane];
                bZ[nb] = g_gwP[((16 + nt) * 32 + kt) * 32 + lane];
                bC[nb] = g_owP[(      nt  * 32 + kt) * 32 + lane];
            }
            #pragma unroll
            for (int mt = 0; mt < 3; ++mt) {
                const uint32* AH = (const uint32*)&ah[mt];
                const uint32* AL = (const uint32*)&al[mt];
                #pragma unroll
                for (int nb = 0; nb < 2; ++nb) {
                    mma8(aR1[mt][nb], AH, bR[nb]); mma8(aR1[mt][nb], AL, bR[nb]);
                    mma8(aZ1[mt][nb], AH, bZ[nb]); mma8(aZ1[mt][nb], AL, bZ[nb]);
                    mma8(aC[mt][nb],  AH, bC[nb]); mma8(aC[mt][nb],  AL, bC[nb]);
                }
            }
        }
        for (int kt = 0; kt < 16; ++kt) {       // h half: A = h1f, gates only
            uint4 ah[3], al[3];
            #pragma unroll
            for (int mt = 0; mt < 3; ++mt) {
                ah[mt] = ((const uint4*)h1f)[((0 * 3 + mt) * 16 + kt) * 32 + lane];
                al[mt] = ((const uint4*)h1f)[((1 * 3 + mt) * 16 + kt) * 32 + lane];
            }
            float2 bR[2], bZ[2];
            #pragma unroll
            for (int nb = 0; nb < 2; ++nb) {
                int nt = 2 * w + nb;
                bR[nb] = g_gwP[((     nt) * 32 + 16 + kt) * 32 + lane];
                bZ[nb] = g_gwP[((16 + nt) * 32 + 16 + kt) * 32 + lane];
            }
            #pragma unroll
            for (int mt = 0; mt < 3; ++mt) {
                const uint32* AH = (const uint32*)&ah[mt];
                const uint32* AL = (const uint32*)&al[mt];
                #pragma unroll
                for (int nb = 0; nb < 2; ++nb) {
                    mma8(aR1[mt][nb], AH, bR[nb]); mma8(aR1[mt][nb], AL, bR[nb]);
                    mma8(aZ1[mt][nb], AH, bZ[nb]); mma8(aZ1[mt][nb], AL, bZ[nb]);
                }
            }
        }
        // (no barrier: epi1 uses only warp-local accs; h1f access is read-read;
        //  rhf old readers finished pre-S5(t-1) and S2/S3 have passed since)

        // ==== layer1 epilogue 1: r,z ; write r*h1 frags ====
        float zz1[3][2][4], hold1[3][2][4];
        #pragma unroll
        for (int mt = 0; mt < 3; ++mt)
            #pragma unroll
            for (int nb = 0; nb < 2; ++nb)
                #pragma unroll
                for (int r = 0; r < 4; ++r) {
                    int m   = mt * 16 + g + 8 * (r >> 1);
                    int col = 16 * w + 8 * nb + 2 * tig + (r & 1);
                    hold1[mt][nb][r] = frag_read2(h1f, 16, mt, col >> 3, m, col);
                    float rr = sigmoidf_(aR1[mt][nb][r]);
                    zz1[mt][nb][r] = sigmoidf_(aZ1[mt][nb][r]);
                    float rh = rr * hold1[mt][nb][r];
                    float hi, lo; tf32_split(rh, hi, lo);
                    frag_write(rhf, 16, 0, mt, col >> 3, m, col, hi);
                    frag_write(rhf, 16, 1, mt, col >> 3, m, col, lo);
                }
        __syncthreads();   // S5: rhf ready; all gates-GEMM h1f reads done

        // ==== candidate r*h half ====
        for (int kt = 0; kt < 16; ++kt) {
            uint4 ah[3], al[3];
            #pragma unroll
            for (int mt = 0; mt < 3; ++mt) {
                ah[mt] = ((const uint4*)rhf)[((0 * 3 + mt) * 16 + kt) * 32 + lane];
                al[mt] = ((const uint4*)rhf)[((1 * 3 + mt) * 16 + kt) * 32 + lane];
            }
            float2 bC[2];
            #pragma unroll
            for (int nb = 0; nb < 2; ++nb)
                bC[nb] = g_owP[((2 * w + nb) * 32 + 16 + kt) * 32 + lane];
            #pragma unroll
            for (int mt = 0; mt < 3; ++mt) {
                const uint32* AH = (const uint32*)&ah[mt];
                const uint32* AL = (const uint32*)&al[mt];
                #pragma unroll
                for (int nb = 0; nb < 2; ++nb) {
                    mma8(aC[mt][nb], AH, bC[nb]); mma8(aC[mt][nb], AL, bC[nb]);
                }
            }
        }

        // ==== layer1 epilogue 2: h1(t) -> h1f + gmem out (STG.64 pairs) ====
        // (h1f writes safe: all gates-GEMM h1f reads ended before S5)
        #pragma unroll
        for (int mt = 0; mt < 3; ++mt)
            #pragma unroll
            for (int nb = 0; nb < 2; ++nb)
                #pragma unroll
                for (int rh = 0; rh < 2; ++rh) {
                    int m  = mt * 16 + g + 8 * rh;
                    int c0 = 16 * w + 8 * nb + 2 * tig;
                    float hn2[2];
                    #pragma unroll
                    for (int c = 0; c < 2; ++c) {
                        int r = rh * 2 + c;
                        float cand = tanhf_(aC[mt][nb][r]);
                        float hn = zz1[mt][nb][r] * hold1[mt][nb][r]
                                 + (1.f - zz1[mt][nb][r]) * cand;
                        float hi, lo; tf32_split(hn, hi, lo);
                        frag_write(h1f, 16, 0, mt, c0 >> 3, m, c0 + c, hi);
                        frag_write(h1f, 16, 1, mt, c0 >> 3, m, c0 + c, lo);
                        hn2[c] = hn;
                    }
                    int bn = bn0 + m;
                    if (bn < BN)
                        *reinterpret_cast<float2*>(out + ((size_t)bn * T_ + t) * H_ + c0)
                            = make_float2(hn2[0], hn2[1]);
                }
        // no trailing barrier: next iteration's first phase only READS
        // (xf staged pre-S5; h0f written pre-S3; h1f next read post-S3(t+1))
    }
}

extern "C" void kernel_launch(void* const* d_in, const int* in_sizes, int n_in,
                              void* d_out, int out_size)
{
    const float* x      = (const float*)d_in[0];
    const float* w_ih   = (const float*)d_in[1];
    const float* w_hh   = (const float*)d_in[2];
    const float* b_ih   = (const float*)d_in[3];
    const float* b_hh   = (const float*)d_in[4];
    const float* gate_w = (const float*)d_in[5];
    const float* gate_b = (const float*)d_in[6];
    const float* out_w  = (const float*)d_in[7];
    const float* out_b  = (const float*)d_in[8];
    float* out = (float*)d_out;

    const int smem = (6144 + 3 * 12288) * 4;   // 172032 B
    cudaFuncSetAttribute(gru_fused, cudaFuncAttributeMaxDynamicSharedMemorySize, smem);

    prepack<<<168, 512>>>(w_ih, w_hh, gate_w, out_w);
    gru_fused<<<NCTA, NTH, smem>>>(x, b_ih, b_hh, gate_b, out_b, out);
}